// round 7
// baseline (speedup 1.0000x reference)
#include <cuda_runtime.h>
#include <math.h>

// ---------------------------------------------------------------------------
// Problem constants
// ---------------------------------------------------------------------------
#define NTOK   8192        // B*H*W tokens
#define CIN    256
#define C2     128
#define HWPOS  1024        // H*W
#define BATCH  8
#define KDENSE (HWPOS*CIN) // 262144
#define KCHUNKS 256        // split-K chunks for dense gate (each 1024 k)

// ---------------------------------------------------------------------------
// Scratch (static __device__ arrays; no allocation anywhere)
// ---------------------------------------------------------------------------
__device__ float g_theta[NTOK * C2];
__device__ float g_phi  [NTOK * C2];
__device__ float g_alpha[NTOK * C2];
__device__ float g_attn [NTOK * C2];
__device__ float g_part [KCHUNKS * BATCH * HWPOS];
__device__ float g_sp   [NTOK];

// ---------------------------------------------------------------------------
// Generic fp32 GEMM: C[M,N] = A[M,K] @ B[K,N] (+bias) with optional fused
// epilogue  out = acc * sp[row] + xres[row*N+col].
// BM=BN=128, BK=8, 256 threads, 8x8 per-thread tile (~1 B LDS per FMA).
// Requires M%128==0, N%128==0, K%8==0.
// ---------------------------------------------------------------------------
__global__ __launch_bounds__(256) void gemm128(
    const float* __restrict__ A, const float* __restrict__ B,
    const float* __restrict__ bias, float* __restrict__ C,
    int M, int N, int K,
    const float* __restrict__ sp, const float* __restrict__ xres)
{
    __shared__ __align__(16) float As[8][128];   // transposed A tile [k][m]
    __shared__ __align__(16) float Bs[8][128];   // B tile [k][n]

    const int tid = threadIdx.x;
    const int tx = tid & 15;       // output col group
    const int ty = tid >> 4;       // output row group
    const int row0 = blockIdx.y * 128;
    const int col0 = blockIdx.x * 128;

    const int arow = tid >> 1;           // 0..127
    const int acol = (tid & 1) * 4;      // 0 or 4
    const int brow = tid >> 5;           // 0..7
    const int bcol = (tid & 31) * 4;     // 0..124

    float acc[8][8];
#pragma unroll
    for (int i = 0; i < 8; i++)
#pragma unroll
        for (int j = 0; j < 8; j++) acc[i][j] = 0.f;

    for (int k0 = 0; k0 < K; k0 += 8) {
        float4 av = *(const float4*)(A + (size_t)(row0 + arow) * K + k0 + acol);
        float4 bv = *(const float4*)(B + (size_t)(k0 + brow) * N + col0 + bcol);
        As[acol + 0][arow] = av.x;
        As[acol + 1][arow] = av.y;
        As[acol + 2][arow] = av.z;
        As[acol + 3][arow] = av.w;
        *(float4*)&Bs[brow][bcol] = bv;
        __syncthreads();

#pragma unroll
        for (int k = 0; k < 8; k++) {
            float4 a0 = *(const float4*)&As[k][ty * 8];
            float4 a1 = *(const float4*)&As[k][ty * 8 + 4];
            float4 b0 = *(const float4*)&Bs[k][tx * 8];
            float4 b1 = *(const float4*)&Bs[k][tx * 8 + 4];
            float ar[8] = {a0.x, a0.y, a0.z, a0.w, a1.x, a1.y, a1.z, a1.w};
            float br[8] = {b0.x, b0.y, b0.z, b0.w, b1.x, b1.y, b1.z, b1.w};
#pragma unroll
            for (int i = 0; i < 8; i++)
#pragma unroll
                for (int j = 0; j < 8; j++)
                    acc[i][j] += ar[i] * br[j];
        }
        __syncthreads();
    }

    const bool fuse = (sp != nullptr);
#pragma unroll
    for (int i = 0; i < 8; i++) {
        int r = row0 + ty * 8 + i;
        float spv = fuse ? sp[r] : 0.f;
#pragma unroll
        for (int jv = 0; jv < 2; jv++) {
            int c = col0 + tx * 8 + jv * 4;
            float4 v;
            v.x = acc[i][jv * 4 + 0];
            v.y = acc[i][jv * 4 + 1];
            v.z = acc[i][jv * 4 + 2];
            v.w = acc[i][jv * 4 + 3];
            if (bias) {
                v.x += bias[c + 0]; v.y += bias[c + 1];
                v.z += bias[c + 2]; v.w += bias[c + 3];
            }
            if (fuse) {
                float4 xv = *(const float4*)(xres + (size_t)r * N + c);
                v.x = v.x * spv + xv.x;
                v.y = v.y * spv + xv.y;
                v.z = v.z * spv + xv.z;
                v.w = v.w * spv + xv.w;
            }
            *(float4*)(C + (size_t)r * N + c) = v;
        }
    }
}

// ---------------------------------------------------------------------------
// Flash attention (no scale):  O = softmax(Q K^T) V
// Q,K,V,O: [8192,128] fp32. Block = 64 query rows, KV tile = 128 keys.
// 256 threads (16x16); each thread: 4 q-rows x 8 keys for S, 4 q-rows x 8 d
// for O. Online softmax with per-row running (m, l).
// Dynamic smem layout:
//   Qs_T[128 d][68]   (64 q + pad4)
//   Ks_T[128 d][132]  (128 keys + pad4)
//   Vs  [128 key][132]
//   Ps  [64 q][132]
// ---------------------------------------------------------------------------
#define ASMEM_WORDS (128*68 + 128*132 + 128*132 + 64*132)
#define ASMEM_BYTES (ASMEM_WORDS * 4)

__global__ __launch_bounds__(256) void attn_kernel(
    const float* __restrict__ Q, const float* __restrict__ Kg,
    const float* __restrict__ V, float* __restrict__ Out)
{
    extern __shared__ __align__(16) float smx[];
    float* Qs = smx;                    // 128*68
    float* Ks = Qs + 128 * 68;          // 128*132
    float* Vs = Ks + 128 * 132;         // 128*132
    float* Ps = Vs + 128 * 132;         // 64*132

    const int tid = threadIdx.x;
    const int tx = tid & 15;
    const int ty = tid >> 4;
    const int q0 = blockIdx.x * 64;

    // Load Q tile transposed: Qs[d][r]
#pragma unroll
    for (int t = 0; t < 8; t++) {
        int e = (tid + t * 256) * 4;         // element index, 0..8188
        int r = e >> 7;
        int d = e & 127;
        float4 v = *(const float4*)(Q + (size_t)(q0 + r) * 128 + d);
        Qs[(d + 0) * 68 + r] = v.x;
        Qs[(d + 1) * 68 + r] = v.y;
        Qs[(d + 2) * 68 + r] = v.z;
        Qs[(d + 3) * 68 + r] = v.w;
    }

    float m[4], l[4], o[4][8];
#pragma unroll
    for (int i = 0; i < 4; i++) {
        m[i] = -INFINITY;
        l[i] = 0.f;
#pragma unroll
        for (int d = 0; d < 8; d++) o[i][d] = 0.f;
    }

    for (int kt = 0; kt < NTOK; kt += 128) {
        __syncthreads();   // previous tile's Ks/Vs/Ps fully consumed

        // Load K transposed + V row-major
#pragma unroll
        for (int t = 0; t < 16; t++) {
            int e = (tid + t * 256) * 4;     // 0..16380
            int r = e >> 7;
            int d = e & 127;
            float4 kv = *(const float4*)(Kg + (size_t)(kt + r) * 128 + d);
            Ks[(d + 0) * 132 + r] = kv.x;
            Ks[(d + 1) * 132 + r] = kv.y;
            Ks[(d + 2) * 132 + r] = kv.z;
            Ks[(d + 3) * 132 + r] = kv.w;
            float4 vv = *(const float4*)(V + (size_t)(kt + r) * 128 + d);
            *(float4*)&Vs[r * 132 + d] = vv;
        }
        __syncthreads();

        // S = Q K^T  (4 rows x 8 cols per thread)
        float s[4][8];
#pragma unroll
        for (int i = 0; i < 4; i++)
#pragma unroll
            for (int j = 0; j < 8; j++) s[i][j] = 0.f;

#pragma unroll 8
        for (int d = 0; d < 128; d++) {
            float4 qa = *(const float4*)&Qs[d * 68 + ty * 4];
            float4 k0 = *(const float4*)&Ks[d * 132 + tx * 8];
            float4 k1 = *(const float4*)&Ks[d * 132 + tx * 8 + 4];
            float qv[4] = {qa.x, qa.y, qa.z, qa.w};
            float kv[8] = {k0.x, k0.y, k0.z, k0.w, k1.x, k1.y, k1.z, k1.w};
#pragma unroll
            for (int i = 0; i < 4; i++)
#pragma unroll
                for (int j = 0; j < 8; j++)
                    s[i][j] += qv[i] * kv[j];
        }

        // Online softmax update + write P
#pragma unroll
        for (int ii = 0; ii < 4; ii++) {
            float rmax = s[ii][0];
#pragma unroll
            for (int j = 1; j < 8; j++) rmax = fmaxf(rmax, s[ii][j]);
#pragma unroll
            for (int off = 8; off > 0; off >>= 1)
                rmax = fmaxf(rmax, __shfl_xor_sync(0xffffffffu, rmax, off));
            float mnew  = fmaxf(m[ii], rmax);
            float scale = __expf(m[ii] - mnew);
            m[ii] = mnew;

            float p[8];
            float psum = 0.f;
#pragma unroll
            for (int j = 0; j < 8; j++) {
                p[j] = __expf(s[ii][j] - mnew);
                psum += p[j];
            }
#pragma unroll
            for (int off = 8; off > 0; off >>= 1)
                psum += __shfl_xor_sync(0xffffffffu, psum, off);
            l[ii] = l[ii] * scale + psum;
#pragma unroll
            for (int d = 0; d < 8; d++) o[ii][d] *= scale;

            float4 p0 = make_float4(p[0], p[1], p[2], p[3]);
            float4 p1 = make_float4(p[4], p[5], p[6], p[7]);
            *(float4*)&Ps[(ty * 4 + ii) * 132 + tx * 8]     = p0;
            *(float4*)&Ps[(ty * 4 + ii) * 132 + tx * 8 + 4] = p1;
        }
        __syncthreads();   // P visible to all columns

        // O += P V   (4 rows x 8 d per thread)
#pragma unroll 4
        for (int j = 0; j < 128; j++) {
            float4 v0 = *(const float4*)&Vs[j * 132 + tx * 8];
            float4 v1 = *(const float4*)&Vs[j * 132 + tx * 8 + 4];
#pragma unroll
            for (int ii = 0; ii < 4; ii++) {
                float p = Ps[(ty * 4 + ii) * 132 + j];
                o[ii][0] += p * v0.x; o[ii][1] += p * v0.y;
                o[ii][2] += p * v0.z; o[ii][3] += p * v0.w;
                o[ii][4] += p * v1.x; o[ii][5] += p * v1.y;
                o[ii][6] += p * v1.z; o[ii][7] += p * v1.w;
            }
        }
    }

    // Normalize and store
#pragma unroll
    for (int ii = 0; ii < 4; ii++) {
        float inv = 1.f / l[ii];
        float4 r0 = make_float4(o[ii][0] * inv, o[ii][1] * inv,
                                o[ii][2] * inv, o[ii][3] * inv);
        float4 r1 = make_float4(o[ii][4] * inv, o[ii][5] * inv,
                                o[ii][6] * inv, o[ii][7] * inv);
        size_t base = (size_t)(q0 + ty * 4 + ii) * 128 + tx * 8;
        *(float4*)(Out + base)     = r0;
        *(float4*)(Out + base + 4) = r1;
    }
}

// ---------------------------------------------------------------------------
// Dense gate, stage 1: split-K partial sums.
// logits[b][j] = sum_k x[b][k] * Wd[k][j].  Grid = 256 k-chunks of 1024.
// Each block: cache x chunk [8][1024] in smem, each thread owns 4 j columns,
// accumulate for all 8 batches. HBM-bound on Wd (1.07 GB read once).
// ---------------------------------------------------------------------------
__global__ __launch_bounds__(256) void dense_partial(
    const float* __restrict__ x, const float* __restrict__ Wd,
    float* __restrict__ part)
{
    __shared__ __align__(16) float xs[BATCH * 1024];
    const int tid = threadIdx.x;
    const int k0 = blockIdx.x * 1024;

#pragma unroll
    for (int t = 0; t < 8; t++) {
        int e = (tid + t * 256) * 4;     // 0..8188
        int b = e >> 10;
        int kk = e & 1023;
        *(float4*)&xs[b * 1024 + kk] =
            *(const float4*)(x + (size_t)b * KDENSE + k0 + kk);
    }
    __syncthreads();

    float4 acc[BATCH];
#pragma unroll
    for (int b = 0; b < BATCH; b++) acc[b] = make_float4(0.f, 0.f, 0.f, 0.f);

    const int j = tid * 4;
#pragma unroll 4
    for (int kk = 0; kk < 1024; kk++) {
        float4 w = *(const float4*)(Wd + (size_t)(k0 + kk) * HWPOS + j);
#pragma unroll
        for (int b = 0; b < BATCH; b++) {
            float xv = xs[b * 1024 + kk];
            acc[b].x += xv * w.x;
            acc[b].y += xv * w.y;
            acc[b].z += xv * w.z;
            acc[b].w += xv * w.w;
        }
    }

#pragma unroll
    for (int b = 0; b < BATCH; b++)
        *(float4*)&part[((size_t)blockIdx.x * BATCH + b) * HWPOS + j] = acc[b];
}

// ---------------------------------------------------------------------------
// Dense gate, stage 2: deterministic fixed-order reduction over chunks,
// then softmax over the 1024 positions of each batch. Grid = 8 (batch).
// ---------------------------------------------------------------------------
__global__ __launch_bounds__(256) void dense_softmax(
    const float* __restrict__ part, const float* __restrict__ bias,
    float* __restrict__ sp)
{
    __shared__ float red[256];
    const int b = blockIdx.x;
    const int tid = threadIdx.x;
    const int j = tid * 4;

    float4 s = *(const float4*)(bias + j);
    for (int kc = 0; kc < KCHUNKS; kc++) {
        float4 p = *(const float4*)(part + ((size_t)kc * BATCH + b) * HWPOS + j);
        s.x += p.x; s.y += p.y; s.z += p.z; s.w += p.w;
    }

    // block max
    float lm = fmaxf(fmaxf(s.x, s.y), fmaxf(s.z, s.w));
    red[tid] = lm;
    __syncthreads();
    for (int off = 128; off > 0; off >>= 1) {
        if (tid < off) red[tid] = fmaxf(red[tid], red[tid + off]);
        __syncthreads();
    }
    float mx = red[0];
    __syncthreads();

    float4 e;
    e.x = __expf(s.x - mx); e.y = __expf(s.y - mx);
    e.z = __expf(s.z - mx); e.w = __expf(s.w - mx);

    red[tid] = e.x + e.y + e.z + e.w;
    __syncthreads();
    for (int off = 128; off > 0; off >>= 1) {
        if (tid < off) red[tid] = red[tid] + red[tid + off];
        __syncthreads();
    }
    float inv = 1.f / red[0];

    e.x *= inv; e.y *= inv; e.z *= inv; e.w *= inv;
    *(float4*)(sp + (size_t)b * HWPOS + j) = e;
}

// ---------------------------------------------------------------------------
// Launcher. Inputs (metadata order):
//   0:x 1:W_theta 2:b_theta 3:W_phi 4:b_phi 5:W_alpha 6:b_alpha
//   7:W_mask 8:W_dense 9:b_dense
// ---------------------------------------------------------------------------
extern "C" void kernel_launch(void* const* d_in, const int* in_sizes, int n_in,
                              void* d_out, int out_size)
{
    (void)in_sizes; (void)n_in; (void)out_size;
    const float* x       = (const float*)d_in[0];
    const float* W_theta = (const float*)d_in[1];
    const float* b_theta = (const float*)d_in[2];
    const float* W_phi   = (const float*)d_in[3];
    const float* b_phi   = (const float*)d_in[4];
    const float* W_alpha = (const float*)d_in[5];
    const float* b_alpha = (const float*)d_in[6];
    const float* W_mask  = (const float*)d_in[7];
    const float* W_dense = (const float*)d_in[8];
    const float* b_dense = (const float*)d_in[9];
    float* out = (float*)d_out;

    float *theta, *phi, *alpha, *attn, *part, *sp;
    cudaGetSymbolAddress((void**)&theta, g_theta);
    cudaGetSymbolAddress((void**)&phi,   g_phi);
    cudaGetSymbolAddress((void**)&alpha, g_alpha);
    cudaGetSymbolAddress((void**)&attn,  g_attn);
    cudaGetSymbolAddress((void**)&part,  g_part);
    cudaGetSymbolAddress((void**)&sp,    g_sp);

    cudaFuncSetAttribute(attn_kernel,
                         cudaFuncAttributeMaxDynamicSharedMemorySize,
                         ASMEM_BYTES);

    // Projections: [8192,256] @ [256,128] + bias
    gemm128<<<dim3(1, 64), 256>>>(x, W_theta, b_theta, theta,
                                  NTOK, C2, CIN, nullptr, nullptr);
    gemm128<<<dim3(1, 64), 256>>>(x, W_phi, b_phi, phi,
                                  NTOK, C2, CIN, nullptr, nullptr);
    gemm128<<<dim3(1, 64), 256>>>(x, W_alpha, b_alpha, alpha,
                                  NTOK, C2, CIN, nullptr, nullptr);

    // Dense spatial gate (independent of attention)
    dense_partial<<<KCHUNKS, 256>>>(x, W_dense, part);
    dense_softmax<<<BATCH, 256>>>(part, b_dense, sp);

    // Flash attention over all 8192 tokens
    attn_kernel<<<NTOK / 64, 256, ASMEM_BYTES>>>(theta, phi, alpha, attn);

    // mod_attention = attn_out @ W_mask, fused: out = mod*sp + x
    gemm128<<<dim3(2, 64), 256>>>(attn, W_mask, nullptr, out,
                                  NTOK, CIN, C2, sp, x);
}

// round 8
// speedup vs baseline: 2.7800x; 2.7800x over previous
#include <cuda_runtime.h>
#include <cuda_bf16.h>
#include <math.h>

// ---------------------------------------------------------------------------
// Problem constants
// ---------------------------------------------------------------------------
#define NTOK   8192
#define CIN    256
#define C2     128
#define HWPOS  1024
#define BATCH  8
#define KDENSE (HWPOS*CIN)     // 262144
#define KCH    1024            // split-K chunks for dense gate
#define KCHUNK 256             // k per chunk
#define NGRP   8               // second-level reduce groups (128 chunks each)

// Attention tiling
#define TQ   64                // q rows per block
#define TK   128               // keys per KV tile
#define ALD  136               // smem row stride (bf16 elems): banks (4g+m) all distinct

// ---------------------------------------------------------------------------
// Scratch (static device arrays; no allocation anywhere)
// ---------------------------------------------------------------------------
__device__ __nv_bfloat16 g_q  [NTOK * C2];     // theta, bf16 row-major
__device__ __nv_bfloat16 g_k  [NTOK * C2];     // phi,   bf16 row-major
__device__ __nv_bfloat16 g_vT [C2 * NTOK];     // alpha^T, bf16 [d][token]
__device__ float g_attn [NTOK * C2];
__device__ float g_part [(size_t)KCH * BATCH * HWPOS];   // 32 MB
__device__ float g_part2[NGRP * BATCH * HWPOS];
__device__ float g_sp   [BATCH * HWPOS];

// ---------------------------------------------------------------------------
// Helpers
// ---------------------------------------------------------------------------
__device__ __forceinline__ void mma16816(float* c, const unsigned* a,
                                         unsigned b0, unsigned b1) {
    asm volatile(
        "mma.sync.aligned.m16n8k16.row.col.f32.bf16.bf16.f32 "
        "{%0,%1,%2,%3}, {%4,%5,%6,%7}, {%8,%9}, {%0,%1,%2,%3};\n"
        : "+f"(c[0]), "+f"(c[1]), "+f"(c[2]), "+f"(c[3])
        : "r"(a[0]), "r"(a[1]), "r"(a[2]), "r"(a[3]), "r"(b0), "r"(b1));
}

__device__ __forceinline__ void cpasync16(void* s, const void* g) {
    unsigned sa = (unsigned)__cvta_generic_to_shared(s);
    asm volatile("cp.async.cg.shared.global [%0], [%1], 16;\n"
                 :: "r"(sa), "l"(g));
}
__device__ __forceinline__ unsigned pack_bf16x2(float lo, float hi) {
    __nv_bfloat162 h = __float22bfloat162_rn(make_float2(lo, hi));
    return *(unsigned*)&h;
}

// ---------------------------------------------------------------------------
// Fused projections: z=0 theta->g_q, z=1 phi->g_k, z=2 alpha->g_vT (transposed)
// C[8192,128] = x[8192,256] @ W[256,128] + b.  BM=128,BN=128,BK=8, 256 thr.
// ---------------------------------------------------------------------------
__global__ __launch_bounds__(256) void proj_kernel(
    const float* __restrict__ x,
    const float* __restrict__ Wt, const float* __restrict__ bt,
    const float* __restrict__ Wp, const float* __restrict__ bp,
    const float* __restrict__ Wa, const float* __restrict__ ba,
    __nv_bfloat16* __restrict__ Qo, __nv_bfloat16* __restrict__ Ko,
    __nv_bfloat16* __restrict__ VTo)
{
    __shared__ __align__(16) float As[8][128];
    __shared__ __align__(16) float Bs[8][128];

    const int z = blockIdx.z;
    const float* B    = (z == 0) ? Wt : (z == 1) ? Wp : Wa;
    const float* bias = (z == 0) ? bt : (z == 1) ? bp : ba;

    const int tid  = threadIdx.x;
    const int tx   = tid & 15;
    const int ty   = tid >> 4;
    const int row0 = blockIdx.y * 128;

    const int arow = tid >> 1;
    const int acol = (tid & 1) * 4;
    const int brow = tid >> 5;
    const int bcol = (tid & 31) * 4;

    float acc[8][8];
#pragma unroll
    for (int i = 0; i < 8; i++)
#pragma unroll
        for (int j = 0; j < 8; j++) acc[i][j] = 0.f;

    for (int k0 = 0; k0 < CIN; k0 += 8) {
        float4 av = *(const float4*)(x + (size_t)(row0 + arow) * CIN + k0 + acol);
        float4 bv = *(const float4*)(B + (size_t)(k0 + brow) * C2 + bcol);
        As[acol + 0][arow] = av.x; As[acol + 1][arow] = av.y;
        As[acol + 2][arow] = av.z; As[acol + 3][arow] = av.w;
        *(float4*)&Bs[brow][bcol] = bv;
        __syncthreads();
#pragma unroll
        for (int k = 0; k < 8; k++) {
            float4 a0 = *(const float4*)&As[k][ty * 8];
            float4 a1 = *(const float4*)&As[k][ty * 8 + 4];
            float4 b0 = *(const float4*)&Bs[k][tx * 8];
            float4 b1 = *(const float4*)&Bs[k][tx * 8 + 4];
            float ar[8] = {a0.x, a0.y, a0.z, a0.w, a1.x, a1.y, a1.z, a1.w};
            float br[8] = {b0.x, b0.y, b0.z, b0.w, b1.x, b1.y, b1.z, b1.w};
#pragma unroll
            for (int i = 0; i < 8; i++)
#pragma unroll
                for (int j = 0; j < 8; j++)
                    acc[i][j] += ar[i] * br[j];
        }
        __syncthreads();
    }

    __nv_bfloat16* Crow = (z == 0) ? Qo : Ko;
#pragma unroll
    for (int i = 0; i < 8; i++) {
        int r = row0 + ty * 8 + i;
#pragma unroll
        for (int jv = 0; jv < 2; jv++) {
            int c = tx * 8 + jv * 4;
            float v0 = acc[i][jv*4+0] + bias[c+0];
            float v1 = acc[i][jv*4+1] + bias[c+1];
            float v2 = acc[i][jv*4+2] + bias[c+2];
            float v3 = acc[i][jv*4+3] + bias[c+3];
            if (z < 2) {
                unsigned p0 = pack_bf16x2(v0, v1);
                unsigned p1 = pack_bf16x2(v2, v3);
                uint2 u = make_uint2(p0, p1);
                *(uint2*)(Crow + (size_t)r * C2 + c) = u;
            } else {
                VTo[(size_t)(c+0) * NTOK + r] = __float2bfloat16(v0);
                VTo[(size_t)(c+1) * NTOK + r] = __float2bfloat16(v1);
                VTo[(size_t)(c+2) * NTOK + r] = __float2bfloat16(v2);
                VTo[(size_t)(c+3) * NTOK + r] = __float2bfloat16(v3);
            }
        }
    }
}

// ---------------------------------------------------------------------------
// Flash attention with bf16 mma.sync, fp32 accum, no scale.
// Block: 128 threads = 4 warps; warp w owns q rows [16w,16w+16).
// KV tile = 128 keys, cp.async double-buffered.
// Smem: Qs[64][ALD] | K0,K1[128][ALD] | V0,V1[128][ALD]  (bf16)
// ---------------------------------------------------------------------------
#define ATTN_SMEM_ELEMS (TQ*ALD + 4*TK*ALD)
#define ATTN_SMEM_BYTES (ATTN_SMEM_ELEMS * 2)

__global__ __launch_bounds__(128) void attn_mma_kernel(
    const __nv_bfloat16* __restrict__ Qg,   // [8192][128]
    const __nv_bfloat16* __restrict__ Kg,   // [8192][128]
    const __nv_bfloat16* __restrict__ VTg,  // [128][8192]
    float* __restrict__ Out)                // [8192][128]
{
    extern __shared__ __align__(16) __nv_bfloat16 sm[];
    __nv_bfloat16* Qs  = sm;                     // TQ*ALD
    __nv_bfloat16* Ksm = Qs + TQ * ALD;          // 2 * TK*ALD
    __nv_bfloat16* Vsm = Ksm + 2 * TK * ALD;     // 2 * TK*ALD

    const int tid  = threadIdx.x;
    const int warp = tid >> 5;
    const int lane = tid & 31;
    const int g    = lane >> 2;    // group id 0..7
    const int mq   = lane & 3;     // thread-in-group 0..3
    const int q0   = blockIdx.x * TQ;
    const int r0   = warp * 16;

    // ---- stage Q tile (64x128 bf16) ----
#pragma unroll
    for (int t = 0; t < 8; t++) {
        int e = (tid + t * 128) * 8;
        int r = e >> 7, d = e & 127;
        *(uint4*)&Qs[r * ALD + d] = *(const uint4*)(Qg + (size_t)(q0 + r) * C2 + d);
    }

    // issue first KV tile (buffer 0) via cp.async
    {
#pragma unroll
        for (int t = 0; t < 16; t++) {
            int e = (tid + t * 128) * 8;
            int r = e >> 7, d = e & 127;
            cpasync16(&Ksm[r * ALD + d], Kg + (size_t)r * C2 + d);
            cpasync16(&Vsm[r * ALD + d], VTg + (size_t)r * NTOK + d);
        }
        asm volatile("cp.async.commit_group;\n");
    }
    __syncthreads();   // Qs visible

    // ---- Q fragments, held for the whole kernel ----
    unsigned qa[8][4];
#pragma unroll
    for (int t = 0; t < 8; t++) {
        int k0 = t * 16;
        qa[t][0] = *(const unsigned*)&Qs[(r0 + g    ) * ALD + k0 + 2 * mq];
        qa[t][1] = *(const unsigned*)&Qs[(r0 + g + 8) * ALD + k0 + 2 * mq];
        qa[t][2] = *(const unsigned*)&Qs[(r0 + g    ) * ALD + k0 + 8 + 2 * mq];
        qa[t][3] = *(const unsigned*)&Qs[(r0 + g + 8) * ALD + k0 + 8 + 2 * mq];
    }

    float m0 = -INFINITY, m1 = -INFINITY, l0 = 0.f, l1 = 0.f;
    float o[16][4];
#pragma unroll
    for (int n = 0; n < 16; n++)
#pragma unroll
        for (int u = 0; u < 4; u++) o[n][u] = 0.f;

    const int NT = NTOK / TK;   // 64
    for (int kt = 0; kt < NT; kt++) {
        const int cur = kt & 1;
        if (kt + 1 < NT) {
            __nv_bfloat16* kd = Ksm + (cur ^ 1) * TK * ALD;
            __nv_bfloat16* vd = Vsm + (cur ^ 1) * TK * ALD;
            const size_t kbase = (size_t)(kt + 1) * TK;
#pragma unroll
            for (int t = 0; t < 16; t++) {
                int e = (tid + t * 128) * 8;
                int r = e >> 7, d = e & 127;
                cpasync16(&kd[r * ALD + d], Kg + (kbase + r) * C2 + d);
                cpasync16(&vd[r * ALD + d], VTg + (size_t)r * NTOK + kbase + d);
            }
            asm volatile("cp.async.commit_group;\n");
            asm volatile("cp.async.wait_group 1;\n");
        } else {
            asm volatile("cp.async.wait_group 0;\n");
        }
        __syncthreads();

        const __nv_bfloat16* Kb = Ksm + cur * TK * ALD;
        const __nv_bfloat16* Vb = Vsm + cur * TK * ALD;

        // ---- S = Q K^T : 16 n-tiles x 8 k-steps ----
        float s[16][4];
#pragma unroll
        for (int j = 0; j < 16; j++) {
            s[j][0] = 0.f; s[j][1] = 0.f; s[j][2] = 0.f; s[j][3] = 0.f;
        }
#pragma unroll
        for (int j = 0; j < 16; j++) {
            const __nv_bfloat16* row = Kb + (8 * j + g) * ALD + 2 * mq;
#pragma unroll
            for (int t = 0; t < 8; t++) {
                unsigned b0 = *(const unsigned*)(row + 16 * t);
                unsigned b1 = *(const unsigned*)(row + 16 * t + 8);
                mma16816(s[j], qa[t], b0, b1);
            }
        }

        // ---- online softmax (rows r0+g and r0+g+8) ----
        float rmax0 = s[0][0], rmax1 = s[0][2];
#pragma unroll
        for (int j = 0; j < 16; j++) {
            rmax0 = fmaxf(rmax0, fmaxf(s[j][0], s[j][1]));
            rmax1 = fmaxf(rmax1, fmaxf(s[j][2], s[j][3]));
        }
        rmax0 = fmaxf(rmax0, __shfl_xor_sync(0xffffffffu, rmax0, 1));
        rmax0 = fmaxf(rmax0, __shfl_xor_sync(0xffffffffu, rmax0, 2));
        rmax1 = fmaxf(rmax1, __shfl_xor_sync(0xffffffffu, rmax1, 1));
        rmax1 = fmaxf(rmax1, __shfl_xor_sync(0xffffffffu, rmax1, 2));

        float mn0 = fmaxf(m0, rmax0), mn1 = fmaxf(m1, rmax1);
        float sc0 = __expf(m0 - mn0), sc1 = __expf(m1 - mn1);
        m0 = mn0; m1 = mn1;

        float rs0 = 0.f, rs1 = 0.f;
#pragma unroll
        for (int j = 0; j < 16; j++) {
            s[j][0] = __expf(s[j][0] - mn0); rs0 += s[j][0];
            s[j][1] = __expf(s[j][1] - mn0); rs0 += s[j][1];
            s[j][2] = __expf(s[j][2] - mn1); rs1 += s[j][2];
            s[j][3] = __expf(s[j][3] - mn1); rs1 += s[j][3];
        }
        rs0 += __shfl_xor_sync(0xffffffffu, rs0, 1);
        rs0 += __shfl_xor_sync(0xffffffffu, rs0, 2);
        rs1 += __shfl_xor_sync(0xffffffffu, rs1, 1);
        rs1 += __shfl_xor_sync(0xffffffffu, rs1, 2);
        l0 = l0 * sc0 + rs0;
        l1 = l1 * sc1 + rs1;
#pragma unroll
        for (int n = 0; n < 16; n++) {
            o[n][0] *= sc0; o[n][1] *= sc0;
            o[n][2] *= sc1; o[n][3] *= sc1;
        }

        // ---- O += P @ V  (P from S regs: C-frag pairs -> A-frag) ----
#pragma unroll
        for (int t = 0; t < 8; t++) {
            unsigned pa[4];
            pa[0] = pack_bf16x2(s[2*t  ][0], s[2*t  ][1]);
            pa[1] = pack_bf16x2(s[2*t  ][2], s[2*t  ][3]);
            pa[2] = pack_bf16x2(s[2*t+1][0], s[2*t+1][1]);
            pa[3] = pack_bf16x2(s[2*t+1][2], s[2*t+1][3]);
            const __nv_bfloat16* vcol = Vb + g * ALD + 16 * t + 2 * mq;
#pragma unroll
            for (int n = 0; n < 16; n++) {
                unsigned b0 = *(const unsigned*)(vcol + (8 * n) * ALD);
                unsigned b1 = *(const unsigned*)(vcol + (8 * n) * ALD + 8);
                mma16816(o[n], pa, b0, b1);
            }
        }
        __syncthreads();   // done with current buffers before they are refilled
    }

    // ---- normalize + store fp32 ----
    float inv0 = 1.f / l0, inv1 = 1.f / l1;
#pragma unroll
    for (int n = 0; n < 16; n++) {
        int c = 8 * n + 2 * mq;
        float2 v0 = make_float2(o[n][0] * inv0, o[n][1] * inv0);
        float2 v1 = make_float2(o[n][2] * inv1, o[n][3] * inv1);
        *(float2*)(Out + (size_t)(q0 + r0 + g    ) * C2 + c) = v0;
        *(float2*)(Out + (size_t)(q0 + r0 + g + 8) * C2 + c) = v1;
    }
}

// ---------------------------------------------------------------------------
// Dense gate stage 1: 1024 chunks of 256 k each.
// ---------------------------------------------------------------------------
__global__ __launch_bounds__(256) void dense_partial(
    const float* __restrict__ x, const float* __restrict__ Wd,
    float* __restrict__ part)
{
    __shared__ __align__(16) float xs[BATCH * KCHUNK];
    const int tid = threadIdx.x;
    const int k0  = blockIdx.x * KCHUNK;

#pragma unroll
    for (int t = 0; t < 2; t++) {
        int e  = (tid + t * 256) * 4;        // 0..2044
        int b  = e >> 8;
        int kk = e & 255;
        *(float4*)&xs[b * KCHUNK + kk] =
            *(const float4*)(x + (size_t)b * KDENSE + k0 + kk);
    }
    __syncthreads();

    float4 acc[BATCH];
#pragma unroll
    for (int b = 0; b < BATCH; b++) acc[b] = make_float4(0.f, 0.f, 0.f, 0.f);

    const int j = tid * 4;
#pragma unroll 4
    for (int kk = 0; kk < KCHUNK; kk++) {
        float4 w = *(const float4*)(Wd + (size_t)(k0 + kk) * HWPOS + j);
#pragma unroll
        for (int b = 0; b < BATCH; b++) {
            float xv = xs[b * KCHUNK + kk];
            acc[b].x += xv * w.x; acc[b].y += xv * w.y;
            acc[b].z += xv * w.z; acc[b].w += xv * w.w;
        }
    }
#pragma unroll
    for (int b = 0; b < BATCH; b++)
        *(float4*)&part[((size_t)blockIdx.x * BATCH + b) * HWPOS + j] = acc[b];
}

// Stage 2a: deterministic reduce of 1024 chunks -> 8 groups.
__global__ __launch_bounds__(256) void dense_reduce(
    const float* __restrict__ part, float* __restrict__ part2)
{
    const int b   = blockIdx.x & 7;
    const int grp = blockIdx.x >> 3;
    const int j   = threadIdx.x * 4;
    float4 s = make_float4(0.f, 0.f, 0.f, 0.f);
    for (int c = 0; c < KCH / NGRP; c++) {
        int kc = grp * (KCH / NGRP) + c;
        float4 p = *(const float4*)(part + ((size_t)kc * BATCH + b) * HWPOS + j);
        s.x += p.x; s.y += p.y; s.z += p.z; s.w += p.w;
    }
    *(float4*)(part2 + ((size_t)grp * BATCH + b) * HWPOS + j) = s;
}

// Stage 2b: final reduce + bias + softmax over 1024 positions per batch.
__global__ __launch_bounds__(256) void dense_softmax(
    const float* __restrict__ part2, const float* __restrict__ bias,
    float* __restrict__ sp)
{
    __shared__ float red[256];
    const int b   = blockIdx.x;
    const int tid = threadIdx.x;
    const int j   = tid * 4;

    float4 s = *(const float4*)(bias + j);
    for (int grp = 0; grp < NGRP; grp++) {
        float4 p = *(const float4*)(part2 + ((size_t)grp * BATCH + b) * HWPOS + j);
        s.x += p.x; s.y += p.y; s.z += p.z; s.w += p.w;
    }

    float lm = fmaxf(fmaxf(s.x, s.y), fmaxf(s.z, s.w));
    red[tid] = lm;
    __syncthreads();
    for (int off = 128; off > 0; off >>= 1) {
        if (tid < off) red[tid] = fmaxf(red[tid], red[tid + off]);
        __syncthreads();
    }
    float mx = red[0];
    __syncthreads();

    float4 e;
    e.x = __expf(s.x - mx); e.y = __expf(s.y - mx);
    e.z = __expf(s.z - mx); e.w = __expf(s.w - mx);
    red[tid] = e.x + e.y + e.z + e.w;
    __syncthreads();
    for (int off = 128; off > 0; off >>= 1) {
        if (tid < off) red[tid] += red[tid + off];
        __syncthreads();
    }
    float inv = 1.f / red[0];
    e.x *= inv; e.y *= inv; e.z *= inv; e.w *= inv;
    *(float4*)(sp + (size_t)b * HWPOS + j) = e;
}

// ---------------------------------------------------------------------------
// Mask GEMM (fp32) with fused epilogue: out = (attn @ W_mask) * sp[row] + x
// ---------------------------------------------------------------------------
__global__ __launch_bounds__(256) void mask_gemm(
    const float* __restrict__ A, const float* __restrict__ B,
    float* __restrict__ C, const float* __restrict__ sp,
    const float* __restrict__ xres)
{
    __shared__ __align__(16) float As[8][128];
    __shared__ __align__(16) float Bs[8][128];

    const int tid  = threadIdx.x;
    const int tx   = tid & 15;
    const int ty   = tid >> 4;
    const int row0 = blockIdx.y * 128;
    const int col0 = blockIdx.x * 128;

    const int arow = tid >> 1;
    const int acol = (tid & 1) * 4;
    const int brow = tid >> 5;
    const int bcol = (tid & 31) * 4;

    float acc[8][8];
#pragma unroll
    for (int i = 0; i < 8; i++)
#pragma unroll
        for (int j = 0; j < 8; j++) acc[i][j] = 0.f;

    for (int k0 = 0; k0 < C2; k0 += 8) {
        float4 av = *(const float4*)(A + (size_t)(row0 + arow) * C2 + k0 + acol);
        float4 bv = *(const float4*)(B + (size_t)(k0 + brow) * CIN + col0 + bcol);
        As[acol + 0][arow] = av.x; As[acol + 1][arow] = av.y;
        As[acol + 2][arow] = av.z; As[acol + 3][arow] = av.w;
        *(float4*)&Bs[brow][bcol] = bv;
        __syncthreads();
#pragma unroll
        for (int k = 0; k < 8; k++) {
            float4 a0 = *(const float4*)&As[k][ty * 8];
            float4 a1 = *(const float4*)&As[k][ty * 8 + 4];
            float4 b0 = *(const float4*)&Bs[k][tx * 8];
            float4 b1 = *(const float4*)&Bs[k][tx * 8 + 4];
            float ar[8] = {a0.x, a0.y, a0.z, a0.w, a1.x, a1.y, a1.z, a1.w};
            float br[8] = {b0.x, b0.y, b0.z, b0.w, b1.x, b1.y, b1.z, b1.w};
#pragma unroll
            for (int i = 0; i < 8; i++)
#pragma unroll
                for (int j = 0; j < 8; j++)
                    acc[i][j] += ar[i] * br[j];
        }
        __syncthreads();
    }

#pragma unroll
    for (int i = 0; i < 8; i++) {
        int r = row0 + ty * 8 + i;
        float spv = sp[r];
#pragma unroll
        for (int jv = 0; jv < 2; jv++) {
            int c = col0 + tx * 8 + jv * 4;
            float4 xv = *(const float4*)(xres + (size_t)r * CIN + c);
            float4 v;
            v.x = acc[i][jv*4+0] * spv + xv.x;
            v.y = acc[i][jv*4+1] * spv + xv.y;
            v.z = acc[i][jv*4+2] * spv + xv.z;
            v.w = acc[i][jv*4+3] * spv + xv.w;
            *(float4*)(C + (size_t)r * CIN + c) = v;
        }
    }
}

// ---------------------------------------------------------------------------
// Launcher. Inputs: 0:x 1:W_theta 2:b_theta 3:W_phi 4:b_phi 5:W_alpha
//                   6:b_alpha 7:W_mask 8:W_dense 9:b_dense
// ---------------------------------------------------------------------------
extern "C" void kernel_launch(void* const* d_in, const int* in_sizes, int n_in,
                              void* d_out, int out_size)
{
    (void)in_sizes; (void)n_in; (void)out_size;
    const float* x       = (const float*)d_in[0];
    const float* W_theta = (const float*)d_in[1];
    const float* b_theta = (const float*)d_in[2];
    const float* W_phi   = (const float*)d_in[3];
    const float* b_phi   = (const float*)d_in[4];
    const float* W_alpha = (const float*)d_in[5];
    const float* b_alpha = (const float*)d_in[6];
    const float* W_mask  = (const float*)d_in[7];
    const float* W_dense = (const float*)d_in[8];
    const float* b_dense = (const float*)d_in[9];
    float* out = (float*)d_out;

    __nv_bfloat16 *q, *k, *vT;
    float *attn, *part, *part2, *sp;
    cudaGetSymbolAddress((void**)&q,     g_q);
    cudaGetSymbolAddress((void**)&k,     g_k);
    cudaGetSymbolAddress((void**)&vT,    g_vT);
    cudaGetSymbolAddress((void**)&attn,  g_attn);
    cudaGetSymbolAddress((void**)&part,  g_part);
    cudaGetSymbolAddress((void**)&part2, g_part2);
    cudaGetSymbolAddress((void**)&sp,    g_sp);

    cudaFuncSetAttribute(attn_mma_kernel,
                         cudaFuncAttributeMaxDynamicSharedMemorySize,
                         ATTN_SMEM_BYTES);

    // Fused projections -> bf16 Q, K, V^T
    proj_kernel<<<dim3(1, 64, 3), 256>>>(x, W_theta, b_theta, W_phi, b_phi,
                                         W_alpha, b_alpha, q, k, vT);

    // Dense spatial gate
    dense_partial<<<KCH, 256>>>(x, W_dense, part);
    dense_reduce<<<NGRP * BATCH, 256>>>(part, part2);
    dense_softmax<<<BATCH, 256>>>(part2, b_dense, sp);

    // Tensor-core flash attention
    attn_mma_kernel<<<NTOK / TQ, 128, ATTN_SMEM_BYTES>>>(q, k, vT, attn);

    // Fused mask GEMM + gating + residual
    mask_gemm<<<dim3(2, 64), 256>>>(attn, W_mask, out, sp, x);
}

// round 11
// speedup vs baseline: 4.4954x; 1.6170x over previous
#include <cuda_runtime.h>
#include <cuda_bf16.h>
#include <math.h>

// ---------------------------------------------------------------------------
// Problem constants
// ---------------------------------------------------------------------------
#define NTOK   8192
#define CIN    256
#define C2     128
#define HWPOS  1024
#define BATCH  8
#define KDENSE (HWPOS*CIN)     // 262144
#define KCH    1024            // split-K chunks for dense gate
#define KCHUNK 256             // k per chunk
#define NGRP   8               // second-level reduce groups

// Attention tiling
#define TQ    64               // q rows per block
#define TK    64               // keys per KV tile
#define NSPL  2                // KV splits
#define ALD   136              // smem stride for 128-wide bf16 rows (68 words ≡ 4 mod 32)
#define VLD   72               // smem stride for 64-wide bf16 rows  (36 words ≡ 4 mod 32)

// ---------------------------------------------------------------------------
// Scratch (static device arrays; no allocation anywhere)
// ---------------------------------------------------------------------------
__device__ __nv_bfloat16 g_q  [NTOK * C2];
__device__ __nv_bfloat16 g_k  [NTOK * C2];
__device__ __nv_bfloat16 g_vT [C2 * NTOK];
__device__ float g_oa  [NSPL][NTOK * C2];      // unnormalized partial O
__device__ float g_ml  [NSPL][NTOK][2];        // per-row (m, l)
__device__ float g_attn[NTOK * C2];
__device__ float g_part [(size_t)KCH * BATCH * HWPOS];
__device__ float g_part2[NGRP * BATCH * HWPOS];
__device__ float g_sp   [BATCH * HWPOS];

// ---------------------------------------------------------------------------
// Helpers
// ---------------------------------------------------------------------------
__device__ __forceinline__ void mma16816(float* c, const unsigned* a,
                                         unsigned b0, unsigned b1) {
    asm volatile(
        "mma.sync.aligned.m16n8k16.row.col.f32.bf16.bf16.f32 "
        "{%0,%1,%2,%3}, {%4,%5,%6,%7}, {%8,%9}, {%0,%1,%2,%3};\n"
        : "+f"(c[0]), "+f"(c[1]), "+f"(c[2]), "+f"(c[3])
        : "r"(a[0]), "r"(a[1]), "r"(a[2]), "r"(a[3]), "r"(b0), "r"(b1));
}
__device__ __forceinline__ void cpasync16(void* s, const void* g) {
    unsigned sa = (unsigned)__cvta_generic_to_shared(s);
    asm volatile("cp.async.cg.shared.global [%0], [%1], 16;\n"
                 :: "r"(sa), "l"(g));
}
__device__ __forceinline__ unsigned pack_bf16x2(float lo, float hi) {
    __nv_bfloat162 h = __float22bfloat162_rn(make_float2(lo, hi));
    return *(unsigned*)&h;
}

// ---------------------------------------------------------------------------
// Fused projections: z=0 theta->g_q, z=1 phi->g_k, z=2 alpha->g_vT (transposed)
// ---------------------------------------------------------------------------
__global__ __launch_bounds__(256) void proj_kernel(
    const float* __restrict__ x,
    const float* __restrict__ Wt, const float* __restrict__ bt,
    const float* __restrict__ Wp, const float* __restrict__ bp,
    const float* __restrict__ Wa, const float* __restrict__ ba,
    __nv_bfloat16* __restrict__ Qo, __nv_bfloat16* __restrict__ Ko,
    __nv_bfloat16* __restrict__ VTo)
{
    __shared__ __align__(16) float As[8][128];
    __shared__ __align__(16) float Bs[8][128];

    const int z = blockIdx.z;
    const float* B    = (z == 0) ? Wt : (z == 1) ? Wp : Wa;
    const float* bias = (z == 0) ? bt : (z == 1) ? bp : ba;

    const int tid  = threadIdx.x;
    const int tx   = tid & 15;
    const int ty   = tid >> 4;
    const int row0 = blockIdx.y * 128;

    const int arow = tid >> 1;
    const int acol = (tid & 1) * 4;
    const int brow = tid >> 5;
    const int bcol = (tid & 31) * 4;

    float acc[8][8];
#pragma unroll
    for (int i = 0; i < 8; i++)
#pragma unroll
        for (int j = 0; j < 8; j++) acc[i][j] = 0.f;

    for (int k0 = 0; k0 < CIN; k0 += 8) {
        float4 av = *(const float4*)(x + (size_t)(row0 + arow) * CIN + k0 + acol);
        float4 bv = *(const float4*)(B + (size_t)(k0 + brow) * C2 + bcol);
        As[acol + 0][arow] = av.x; As[acol + 1][arow] = av.y;
        As[acol + 2][arow] = av.z; As[acol + 3][arow] = av.w;
        *(float4*)&Bs[brow][bcol] = bv;
        __syncthreads();
#pragma unroll
        for (int k = 0; k < 8; k++) {
            float4 a0 = *(const float4*)&As[k][ty * 8];
            float4 a1 = *(const float4*)&As[k][ty * 8 + 4];
            float4 b0 = *(const float4*)&Bs[k][tx * 8];
            float4 b1 = *(const float4*)&Bs[k][tx * 8 + 4];
            float ar[8] = {a0.x, a0.y, a0.z, a0.w, a1.x, a1.y, a1.z, a1.w};
            float br[8] = {b0.x, b0.y, b0.z, b0.w, b1.x, b1.y, b1.z, b1.w};
#pragma unroll
            for (int i = 0; i < 8; i++)
#pragma unroll
                for (int j = 0; j < 8; j++)
                    acc[i][j] += ar[i] * br[j];
        }
        __syncthreads();
    }

    __nv_bfloat16* Crow = (z == 0) ? Qo : Ko;
#pragma unroll
    for (int i = 0; i < 8; i++) {
        int r = row0 + ty * 8 + i;
#pragma unroll
        for (int jv = 0; jv < 2; jv++) {
            int c = tx * 8 + jv * 4;
            float v0 = acc[i][jv*4+0] + bias[c+0];
            float v1 = acc[i][jv*4+1] + bias[c+1];
            float v2 = acc[i][jv*4+2] + bias[c+2];
            float v3 = acc[i][jv*4+3] + bias[c+3];
            if (z < 2) {
                uint2 u = make_uint2(pack_bf16x2(v0, v1), pack_bf16x2(v2, v3));
                *(uint2*)(Crow + (size_t)r * C2 + c) = u;
            } else {
                VTo[(size_t)(c+0) * NTOK + r] = __float2bfloat16(v0);
                VTo[(size_t)(c+1) * NTOK + r] = __float2bfloat16(v1);
                VTo[(size_t)(c+2) * NTOK + r] = __float2bfloat16(v2);
                VTo[(size_t)(c+3) * NTOK + r] = __float2bfloat16(v3);
            }
        }
    }
}

// ---------------------------------------------------------------------------
// Split-KV flash attention, bf16 mma, fp32 accum.
// Grid (NTOK/TQ, NSPL). Block = 128 threads (4 warps), warp owns 16 q rows.
// Each split covers NTOK/NSPL keys in TK=64 tiles, double-buffered cp.async.
// Emits unnormalized O and per-row (m, l).
// Smem: Qs[64][ALD] | K0,K1[64][ALD] | V0,V1[128][VLD]   (bf16)
// ---------------------------------------------------------------------------
#define ATTN_SMEM_ELEMS (TQ*ALD + 2*TK*ALD + 2*C2*VLD)
#define ATTN_SMEM_BYTES (ATTN_SMEM_ELEMS * 2)

__global__ __launch_bounds__(128) void attn_mma_kernel(
    const __nv_bfloat16* __restrict__ Qg,
    const __nv_bfloat16* __restrict__ Kg,
    const __nv_bfloat16* __restrict__ VTg,
    float* __restrict__ Oa,     // [NSPL][NTOK*C2]
    float* __restrict__ Ml)     // [NSPL][NTOK][2]
{
    extern __shared__ __align__(16) __nv_bfloat16 sm[];
    __nv_bfloat16* Qs  = sm;                    // TQ*ALD
    __nv_bfloat16* Ksm = Qs + TQ * ALD;         // 2 * TK*ALD
    __nv_bfloat16* Vsm = Ksm + 2 * TK * ALD;    // 2 * C2*VLD

    const int tid  = threadIdx.x;
    const int warp = tid >> 5;
    const int lane = tid & 31;
    const int g    = lane >> 2;
    const int mq   = lane & 3;
    const int q0   = blockIdx.x * TQ;
    const int spl  = blockIdx.y;
    const int kofs = spl * (NTOK / NSPL);
    const int r0   = warp * 16;

    // stage Q tile (64 x 128 bf16)
#pragma unroll
    for (int t = 0; t < 8; t++) {
        int e = (tid + t * 128) * 8;
        int r = e >> 7, d = e & 127;
        *(uint4*)&Qs[r * ALD + d] = *(const uint4*)(Qg + (size_t)(q0 + r) * C2 + d);
    }

    // prefetch first KV tile into buffer 0
    {
        const size_t kb = (size_t)kofs;
#pragma unroll
        for (int t = 0; t < 8; t++) {       // K: 64 rows x 256 B
            int e = (tid + t * 128) * 8;
            int r = e >> 7, d = e & 127;
            cpasync16(&Ksm[r * ALD + d], Kg + (kb + r) * C2 + d);
        }
#pragma unroll
        for (int t = 0; t < 8; t++) {       // V: 128 dims x 128 B
            int e = (tid + t * 128) * 8;
            int r = e >> 6, d = e & 63;
            cpasync16(&Vsm[r * VLD + d], VTg + (size_t)r * NTOK + kb + d);
        }
        asm volatile("cp.async.commit_group;\n");
    }
    __syncthreads();   // Qs visible

    // Q fragments held in registers for the whole kernel
    unsigned qa[8][4];
#pragma unroll
    for (int t = 0; t < 8; t++) {
        int k0 = t * 16;
        qa[t][0] = *(const unsigned*)&Qs[(r0 + g    ) * ALD + k0 + 2 * mq];
        qa[t][1] = *(const unsigned*)&Qs[(r0 + g + 8) * ALD + k0 + 2 * mq];
        qa[t][2] = *(const unsigned*)&Qs[(r0 + g    ) * ALD + k0 + 8 + 2 * mq];
        qa[t][3] = *(const unsigned*)&Qs[(r0 + g + 8) * ALD + k0 + 8 + 2 * mq];
    }

    float m0 = -INFINITY, m1 = -INFINITY, l0 = 0.f, l1 = 0.f;
    float o[16][4];
#pragma unroll
    for (int n = 0; n < 16; n++)
#pragma unroll
        for (int u = 0; u < 4; u++) o[n][u] = 0.f;

    const int NT = (NTOK / NSPL) / TK;   // 64 tiles
    for (int kt = 0; kt < NT; kt++) {
        const int cur = kt & 1;
        if (kt + 1 < NT) {
            __nv_bfloat16* kd = Ksm + (cur ^ 1) * TK * ALD;
            __nv_bfloat16* vd = Vsm + (cur ^ 1) * C2 * VLD;
            const size_t kb = (size_t)kofs + (size_t)(kt + 1) * TK;
#pragma unroll
            for (int t = 0; t < 8; t++) {
                int e = (tid + t * 128) * 8;
                int r = e >> 7, d = e & 127;
                cpasync16(&kd[r * ALD + d], Kg + (kb + r) * C2 + d);
            }
#pragma unroll
            for (int t = 0; t < 8; t++) {
                int e = (tid + t * 128) * 8;
                int r = e >> 6, d = e & 63;
                cpasync16(&vd[r * VLD + d], VTg + (size_t)r * NTOK + kb + d);
            }
            asm volatile("cp.async.commit_group;\n");
            asm volatile("cp.async.wait_group 1;\n");
        } else {
            asm volatile("cp.async.wait_group 0;\n");
        }
        __syncthreads();

        const __nv_bfloat16* Kb = Ksm + cur * TK * ALD;
        const __nv_bfloat16* Vb = Vsm + cur * C2 * VLD;

        // S = Q K^T : 8 n-tiles x 8 k-steps
        float s[8][4];
#pragma unroll
        for (int j = 0; j < 8; j++) {
            s[j][0] = 0.f; s[j][1] = 0.f; s[j][2] = 0.f; s[j][3] = 0.f;
        }
#pragma unroll
        for (int j = 0; j < 8; j++) {
            const __nv_bfloat16* row = Kb + (8 * j + g) * ALD + 2 * mq;
#pragma unroll
            for (int t = 0; t < 8; t++) {
                unsigned b0 = *(const unsigned*)(row + 16 * t);
                unsigned b1 = *(const unsigned*)(row + 16 * t + 8);
                mma16816(s[j], qa[t], b0, b1);
            }
        }

        // online softmax for rows r0+g, r0+g+8
        float rmax0 = s[0][0], rmax1 = s[0][2];
#pragma unroll
        for (int j = 0; j < 8; j++) {
            rmax0 = fmaxf(rmax0, fmaxf(s[j][0], s[j][1]));
            rmax1 = fmaxf(rmax1, fmaxf(s[j][2], s[j][3]));
        }
        rmax0 = fmaxf(rmax0, __shfl_xor_sync(0xffffffffu, rmax0, 1));
        rmax0 = fmaxf(rmax0, __shfl_xor_sync(0xffffffffu, rmax0, 2));
        rmax1 = fmaxf(rmax1, __shfl_xor_sync(0xffffffffu, rmax1, 1));
        rmax1 = fmaxf(rmax1, __shfl_xor_sync(0xffffffffu, rmax1, 2));

        float mn0 = fmaxf(m0, rmax0), mn1 = fmaxf(m1, rmax1);
        float sc0 = __expf(m0 - mn0), sc1 = __expf(m1 - mn1);
        m0 = mn0; m1 = mn1;

        float rs0 = 0.f, rs1 = 0.f;
#pragma unroll
        for (int j = 0; j < 8; j++) {
            s[j][0] = __expf(s[j][0] - mn0); rs0 += s[j][0];
            s[j][1] = __expf(s[j][1] - mn0); rs0 += s[j][1];
            s[j][2] = __expf(s[j][2] - mn1); rs1 += s[j][2];
            s[j][3] = __expf(s[j][3] - mn1); rs1 += s[j][3];
        }
        rs0 += __shfl_xor_sync(0xffffffffu, rs0, 1);
        rs0 += __shfl_xor_sync(0xffffffffu, rs0, 2);
        rs1 += __shfl_xor_sync(0xffffffffu, rs1, 1);
        rs1 += __shfl_xor_sync(0xffffffffu, rs1, 2);
        l0 = l0 * sc0 + rs0;
        l1 = l1 * sc1 + rs1;
#pragma unroll
        for (int n = 0; n < 16; n++) {
            o[n][0] *= sc0; o[n][1] *= sc0;
            o[n][2] *= sc1; o[n][3] *= sc1;
        }

        // O += P @ V  (P re-packed from S regs; k = 64 keys -> 4 k-steps)
#pragma unroll
        for (int t = 0; t < 4; t++) {
            unsigned pa[4];
            pa[0] = pack_bf16x2(s[2*t  ][0], s[2*t  ][1]);
            pa[1] = pack_bf16x2(s[2*t  ][2], s[2*t  ][3]);
            pa[2] = pack_bf16x2(s[2*t+1][0], s[2*t+1][1]);
            pa[3] = pack_bf16x2(s[2*t+1][2], s[2*t+1][3]);
            const __nv_bfloat16* vcol = Vb + g * VLD + 16 * t + 2 * mq;
#pragma unroll
            for (int n = 0; n < 16; n++) {
                unsigned b0 = *(const unsigned*)(vcol + (8 * n) * VLD);
                unsigned b1 = *(const unsigned*)(vcol + (8 * n) * VLD + 8);
                mma16816(o[n], pa, b0, b1);
            }
        }
        __syncthreads();   // buffers consumed before refill next iteration
    }

    // store unnormalized O + (m, l)
    float* Op = Oa + (size_t)spl * NTOK * C2;
#pragma unroll
    for (int n = 0; n < 16; n++) {
        int c = 8 * n + 2 * mq;
        *(float2*)(Op + (size_t)(q0 + r0 + g    ) * C2 + c) = make_float2(o[n][0], o[n][1]);
        *(float2*)(Op + (size_t)(q0 + r0 + g + 8) * C2 + c) = make_float2(o[n][2], o[n][3]);
    }
    if (mq == 0) {
        float* mlp = Ml + (size_t)spl * NTOK * 2;
        *(float2*)(mlp + (size_t)(q0 + r0 + g    ) * 2) = make_float2(m0, l0);
        *(float2*)(mlp + (size_t)(q0 + r0 + g + 8) * 2) = make_float2(m1, l1);
    }
}

// ---------------------------------------------------------------------------
// Merge the NSPL=2 split-KV partials: log-sum-exp combine.
// ---------------------------------------------------------------------------
__global__ __launch_bounds__(256) void attn_merge(
    const float* __restrict__ Oa, const float* __restrict__ Ml,
    float* __restrict__ Out)
{
    const int tid = blockIdx.x * 256 + threadIdx.x;   // 32768 threads
#pragma unroll
    for (int t = 0; t < 8; t++) {
        int idx = (tid + t * 32768) * 4;
        int row = idx >> 7;
        float2 ml1 = *(const float2*)(Ml + (size_t)row * 2);
        float2 ml2 = *(const float2*)(Ml + (size_t)(NTOK + row) * 2);
        float mm = fmaxf(ml1.x, ml2.x);
        float w1 = __expf(ml1.x - mm);
        float w2 = __expf(ml2.x - mm);
        float inv = 1.f / (w1 * ml1.y + w2 * ml2.y);
        w1 *= inv; w2 *= inv;
        float4 o1 = *(const float4*)(Oa + idx);
        float4 o2 = *(const float4*)(Oa + (size_t)NTOK * C2 + idx);
        float4 r;
        r.x = o1.x * w1 + o2.x * w2;
        r.y = o1.y * w1 + o2.y * w2;
        r.z = o1.z * w1 + o2.z * w2;
        r.w = o1.w * w1 + o2.w * w2;
        *(float4*)(Out + idx) = r;
    }
}

// ---------------------------------------------------------------------------
// Dense gate stage 1: 1024 chunks of 256 k each.
// ---------------------------------------------------------------------------
__global__ __launch_bounds__(256) void dense_partial(
    const float* __restrict__ x, const float* __restrict__ Wd,
    float* __restrict__ part)
{
    __shared__ __align__(16) float xs[BATCH * KCHUNK];
    const int tid = threadIdx.x;
    const int k0  = blockIdx.x * KCHUNK;

#pragma unroll
    for (int t = 0; t < 2; t++) {
        int e  = (tid + t * 256) * 4;
        int b  = e >> 8;
        int kk = e & 255;
        *(float4*)&xs[b * KCHUNK + kk] =
            *(const float4*)(x + (size_t)b * KDENSE + k0 + kk);
    }
    __syncthreads();

    float4 acc[BATCH];
#pragma unroll
    for (int b = 0; b < BATCH; b++) acc[b] = make_float4(0.f, 0.f, 0.f, 0.f);

    const int j = tid * 4;
#pragma unroll 4
    for (int kk = 0; kk < KCHUNK; kk++) {
        float4 w = *(const float4*)(Wd + (size_t)(k0 + kk) * HWPOS + j);
#pragma unroll
        for (int b = 0; b < BATCH; b++) {
            float xv = xs[b * KCHUNK + kk];
            acc[b].x += xv * w.x; acc[b].y += xv * w.y;
            acc[b].z += xv * w.z; acc[b].w += xv * w.w;
        }
    }
#pragma unroll
    for (int b = 0; b < BATCH; b++)
        *(float4*)&part[((size_t)blockIdx.x * BATCH + b) * HWPOS + j] = acc[b];
}

__global__ __launch_bounds__(256) void dense_reduce(
    const float* __restrict__ part, float* __restrict__ part2)
{
    const int b   = blockIdx.x & 7;
    const int grp = blockIdx.x >> 3;
    const int j   = threadIdx.x * 4;
    float4 s = make_float4(0.f, 0.f, 0.f, 0.f);
    for (int c = 0; c < KCH / NGRP; c++) {
        int kc = grp * (KCH / NGRP) + c;
        float4 p = *(const float4*)(part + ((size_t)kc * BATCH + b) * HWPOS + j);
        s.x += p.x; s.y += p.y; s.z += p.z; s.w += p.w;
    }
    *(float4*)(part2 + ((size_t)grp * BATCH + b) * HWPOS + j) = s;
}

__global__ __launch_bounds__(256) void dense_softmax(
    const float* __restrict__ part2, const float* __restrict__ bias,
    float* __restrict__ sp)
{
    __shared__ float red[256];
    const int b   = blockIdx.x;
    const int tid = threadIdx.x;
    const int j   = tid * 4;

    float4 s = *(const float4*)(bias + j);
    for (int grp = 0; grp < NGRP; grp++) {
        float4 p = *(const float4*)(part2 + ((size_t)grp * BATCH + b) * HWPOS + j);
        s.x += p.x; s.y += p.y; s.z += p.z; s.w += p.w;
    }

    float lm = fmaxf(fmaxf(s.x, s.y), fmaxf(s.z, s.w));
    red[tid] = lm;
    __syncthreads();
    for (int off = 128; off > 0; off >>= 1) {
        if (tid < off) red[tid] = fmaxf(red[tid], red[tid + off]);
        __syncthreads();
    }
    float mx = red[0];
    __syncthreads();

    float4 e;
    e.x = __expf(s.x - mx); e.y = __expf(s.y - mx);
    e.z = __expf(s.z - mx); e.w = __expf(s.w - mx);
    red[tid] = e.x + e.y + e.z + e.w;
    __syncthreads();
    for (int off = 128; off > 0; off >>= 1) {
        if (tid < off) red[tid] += red[tid + off];
        __syncthreads();
    }
    float inv = 1.f / red[0];
    e.x *= inv; e.y *= inv; e.z *= inv; e.w *= inv;
    *(float4*)(sp + (size_t)b * HWPOS + j) = e;
}

// ---------------------------------------------------------------------------
// Mask GEMM (fp32), fused epilogue: out = (attn @ W_mask) * sp[row] + x
// ---------------------------------------------------------------------------
__global__ __launch_bounds__(256) void mask_gemm(
    const float* __restrict__ A, const float* __restrict__ B,
    float* __restrict__ C, const float* __restrict__ sp,
    const float* __restrict__ xres)
{
    __shared__ __align__(16) float As[8][128];
    __shared__ __align__(16) float Bs[8][128];

    const int tid  = threadIdx.x;
    const int tx   = tid & 15;
    const int ty   = tid >> 4;
    const int row0 = blockIdx.y * 128;
    const int col0 = blockIdx.x * 128;

    const int arow = tid >> 1;
    const int acol = (tid & 1) * 4;
    const int brow = tid >> 5;
    const int bcol = (tid & 31) * 4;

    float acc[8][8];
#pragma unroll
    for (int i = 0; i < 8; i++)
#pragma unroll
        for (int j = 0; j < 8; j++) acc[i][j] = 0.f;

    for (int k0 = 0; k0 < C2; k0 += 8) {
        float4 av = *(const float4*)(A + (size_t)(row0 + arow) * C2 + k0 + acol);
        float4 bv = *(const float4*)(B + (size_t)(k0 + brow) * CIN + col0 + bcol);
        As[acol + 0][arow] = av.x; As[acol + 1][arow] = av.y;
        As[acol + 2][arow] = av.z; As[acol + 3][arow] = av.w;
        *(float4*)&Bs[brow][bcol] = bv;
        __syncthreads();
#pragma unroll
        for (int k = 0; k < 8; k++) {
            float4 a0 = *(const float4*)&As[k][ty * 8];
            float4 a1 = *(const float4*)&As[k][ty * 8 + 4];
            float4 b0 = *(const float4*)&Bs[k][tx * 8];
            float4 b1 = *(const float4*)&Bs[k][tx * 8 + 4];
            float ar[8] = {a0.x, a0.y, a0.z, a0.w, a1.x, a1.y, a1.z, a1.w};
            float br[8] = {b0.x, b0.y, b0.z, b0.w, b1.x, b1.y, b1.z, b1.w};
#pragma unroll
            for (int i = 0; i < 8; i++)
#pragma unroll
                for (int j = 0; j < 8; j++)
                    acc[i][j] += ar[i] * br[j];
        }
        __syncthreads();
    }

#pragma unroll
    for (int i = 0; i < 8; i++) {
        int r = row0 + ty * 8 + i;
        float spv = sp[r];
#pragma unroll
        for (int jv = 0; jv < 2; jv++) {
            int c = col0 + tx * 8 + jv * 4;
            float4 xv = *(const float4*)(xres + (size_t)r * CIN + c);
            float4 v;
            v.x = acc[i][jv*4+0] * spv + xv.x;
            v.y = acc[i][jv*4+1] * spv + xv.y;
            v.z = acc[i][jv*4+2] * spv + xv.z;
            v.w = acc[i][jv*4+3] * spv + xv.w;
            *(float4*)(C + (size_t)r * CIN + c) = v;
        }
    }
}

// ---------------------------------------------------------------------------
// Launcher with fork-join stream overlap:
//   stream0 (capture origin): proj -> attn -> merge -> [wait sp] -> mask
//   stream1:                  [wait fork] dense_partial -> reduce -> softmax
// ---------------------------------------------------------------------------
static cudaStream_t s_aux = nullptr;
static cudaEvent_t  s_evFork = nullptr, s_evJoin = nullptr;

extern "C" void kernel_launch(void* const* d_in, const int* in_sizes, int n_in,
                              void* d_out, int out_size)
{
    (void)in_sizes; (void)n_in; (void)out_size;
    const float* x       = (const float*)d_in[0];
    const float* W_theta = (const float*)d_in[1];
    const float* b_theta = (const float*)d_in[2];
    const float* W_phi   = (const float*)d_in[3];
    const float* b_phi   = (const float*)d_in[4];
    const float* W_alpha = (const float*)d_in[5];
    const float* b_alpha = (const float*)d_in[6];
    const float* W_mask  = (const float*)d_in[7];
    const float* W_dense = (const float*)d_in[8];
    const float* b_dense = (const float*)d_in[9];
    float* out = (float*)d_out;

    if (!s_aux) {
        cudaStreamCreateWithFlags(&s_aux, cudaStreamNonBlocking);
        cudaEventCreateWithFlags(&s_evFork, cudaEventDisableTiming);
        cudaEventCreateWithFlags(&s_evJoin, cudaEventDisableTiming);
    }

    __nv_bfloat16 *q, *k, *vT;
    float *oa, *ml, *attn, *part, *part2, *sp;
    cudaGetSymbolAddress((void**)&q,     g_q);
    cudaGetSymbolAddress((void**)&k,     g_k);
    cudaGetSymbolAddress((void**)&vT,    g_vT);
    cudaGetSymbolAddress((void**)&oa,    g_oa);
    cudaGetSymbolAddress((void**)&ml,    g_ml);
    cudaGetSymbolAddress((void**)&attn,  g_attn);
    cudaGetSymbolAddress((void**)&part,  g_part);
    cudaGetSymbolAddress((void**)&part2, g_part2);
    cudaGetSymbolAddress((void**)&sp,    g_sp);

    cudaFuncSetAttribute(attn_mma_kernel,
                         cudaFuncAttributeMaxDynamicSharedMemorySize,
                         ATTN_SMEM_BYTES);

    // ---- fork: dense chain on auxiliary stream ----
    cudaEventRecord(s_evFork, 0);
    cudaStreamWaitEvent(s_aux, s_evFork, 0);
    dense_partial<<<KCH, 256, 0, s_aux>>>(x, W_dense, part);
    dense_reduce<<<NGRP * BATCH, 256, 0, s_aux>>>(part, part2);
    dense_softmax<<<BATCH, 256, 0, s_aux>>>(part2, b_dense, sp);
    cudaEventRecord(s_evJoin, s_aux);

    // ---- main chain on capture-origin stream ----
    proj_kernel<<<dim3(1, 64, 3), 256>>>(x, W_theta, b_theta, W_phi, b_phi,
                                         W_alpha, b_alpha, q, k, vT);
    attn_mma_kernel<<<dim3(NTOK / TQ, NSPL), 128, ATTN_SMEM_BYTES>>>(
        q, k, vT, oa, ml);
    attn_merge<<<128, 256>>>(oa, ml, attn);

    // ---- join, then fused mask GEMM + gate + residual ----
    cudaStreamWaitEvent(0, s_evJoin, 0);
    mask_gemm<<<dim3(2, 64), 256>>>(attn, W_mask, out, sp, x);
}

// round 12
// speedup vs baseline: 4.8532x; 1.0796x over previous
#include <cuda_runtime.h>
#include <cuda_bf16.h>
#include <math.h>

// ---------------------------------------------------------------------------
// Problem constants
// ---------------------------------------------------------------------------
#define NTOK   8192
#define CIN    256
#define C2     128
#define HWPOS  1024
#define BATCH  8
#define KDENSE (HWPOS*CIN)     // 262144
#define KCH    1024            // split-K chunks for dense gate
#define KCHUNK 256             // k per chunk
#define NGRP   8               // second-level reduce groups

// Attention tiling
#define TQ    64               // q rows per block
#define TK    64               // keys per KV tile
#define NSPL  2                // KV splits
#define ALD   136              // smem stride, 128-wide bf16 rows (68 words ≡ 4 mod 32)
#define VLD   72               // smem stride, 64-wide bf16 rows  (36 words ≡ 4 mod 32)

// proj / mask tiling
#define XLD   264              // x-tile row stride (bf16), 256-wide (+8 pad)
#define WLD   136              // weight smem row stride (bf16), 128-wide (+8 pad)

// ---------------------------------------------------------------------------
// Scratch (static device arrays; no allocation anywhere)
// ---------------------------------------------------------------------------
__device__ __nv_bfloat16 g_xb [NTOK * CIN];    // x in bf16
__device__ __nv_bfloat16 g_wtb[CIN * C2];
__device__ __nv_bfloat16 g_wpb[CIN * C2];
__device__ __nv_bfloat16 g_wab[CIN * C2];
__device__ __nv_bfloat16 g_wmb[C2 * CIN];      // W_mask bf16
__device__ __nv_bfloat16 g_q  [NTOK * C2];
__device__ __nv_bfloat16 g_k  [NTOK * C2];
__device__ __nv_bfloat16 g_vT [C2 * NTOK];
__device__ float g_oa  [NSPL][NTOK * C2];      // unnormalized partial O
__device__ float g_ml  [NSPL][NTOK][2];        // per-row (m, l)
__device__ __nv_bfloat16 g_attnb[NTOK * C2];   // merged attention, bf16
__device__ float g_part [(size_t)KCH * BATCH * HWPOS];
__device__ float g_part2[NGRP * BATCH * HWPOS];
__device__ float g_sp   [BATCH * HWPOS];

// ---------------------------------------------------------------------------
// Helpers
// ---------------------------------------------------------------------------
__device__ __forceinline__ void mma16816(float* c, const unsigned* a,
                                         unsigned b0, unsigned b1) {
    asm volatile(
        "mma.sync.aligned.m16n8k16.row.col.f32.bf16.bf16.f32 "
        "{%0,%1,%2,%3}, {%4,%5,%6,%7}, {%8,%9}, {%0,%1,%2,%3};\n"
        : "+f"(c[0]), "+f"(c[1]), "+f"(c[2]), "+f"(c[3])
        : "r"(a[0]), "r"(a[1]), "r"(a[2]), "r"(a[3]), "r"(b0), "r"(b1));
}
__device__ __forceinline__ void ldsm4(unsigned& r0, unsigned& r1,
                                      unsigned& r2, unsigned& r3, unsigned a) {
    asm volatile("ldmatrix.sync.aligned.m8n8.x4.shared.b16 {%0,%1,%2,%3}, [%4];"
                 : "=r"(r0), "=r"(r1), "=r"(r2), "=r"(r3) : "r"(a));
}
__device__ __forceinline__ void ldsm4t(unsigned& r0, unsigned& r1,
                                       unsigned& r2, unsigned& r3, unsigned a) {
    asm volatile("ldmatrix.sync.aligned.m8n8.x4.trans.shared.b16 {%0,%1,%2,%3}, [%4];"
                 : "=r"(r0), "=r"(r1), "=r"(r2), "=r"(r3) : "r"(a));
}
__device__ __forceinline__ void cpasync16(void* s, const void* g) {
    unsigned sa = (unsigned)__cvta_generic_to_shared(s);
    asm volatile("cp.async.cg.shared.global [%0], [%1], 16;\n"
                 :: "r"(sa), "l"(g));
}
__device__ __forceinline__ unsigned pack_bf16x2(float lo, float hi) {
    __nv_bfloat162 h = __float22bfloat162_rn(make_float2(lo, hi));
    return *(unsigned*)&h;
}

// ---------------------------------------------------------------------------
// fp32 -> bf16 conversions
// ---------------------------------------------------------------------------
__global__ __launch_bounds__(256) void conv_x(
    const float* __restrict__ x, __nv_bfloat16* __restrict__ xb)
{
    int i = (blockIdx.x * 256 + threadIdx.x) * 8;     // grid 1024 -> 2M elems
    float4 a = *(const float4*)(x + i);
    float4 b = *(const float4*)(x + i + 4);
    uint4 u;
    u.x = pack_bf16x2(a.x, a.y); u.y = pack_bf16x2(a.z, a.w);
    u.z = pack_bf16x2(b.x, b.y); u.w = pack_bf16x2(b.z, b.w);
    *(uint4*)(xb + i) = u;
}

__global__ __launch_bounds__(256) void conv_w(
    const float* __restrict__ Wt, const float* __restrict__ Wp,
    const float* __restrict__ Wa, const float* __restrict__ Wm,
    __nv_bfloat16* __restrict__ Wtb, __nv_bfloat16* __restrict__ Wpb,
    __nv_bfloat16* __restrict__ Wab, __nv_bfloat16* __restrict__ Wmb)
{
    int i = (blockIdx.x * 256 + threadIdx.x) * 8;     // grid 64 -> 131072 elems
    int seg = i >> 15;
    int off = i & 32767;
    const float* src = (seg == 0) ? Wt : (seg == 1) ? Wp : (seg == 2) ? Wa : Wm;
    __nv_bfloat16* dst = (seg == 0) ? Wtb : (seg == 1) ? Wpb : (seg == 2) ? Wab : Wmb;
    float4 a = *(const float4*)(src + off);
    float4 b = *(const float4*)(src + off + 4);
    uint4 u;
    u.x = pack_bf16x2(a.x, a.y); u.y = pack_bf16x2(a.z, a.w);
    u.z = pack_bf16x2(b.x, b.y); u.w = pack_bf16x2(b.z, b.w);
    *(uint4*)(dst + off) = u;
}

// ---------------------------------------------------------------------------
// Tensor-core projections: C[8192,128] = xb[8192,256] @ Wb[256,128] + bias.
// Grid (128, 1, 3): x = m-tile (64 rows), z = {theta->Q, phi->K, alpha->VT}.
// Block = 128 threads (4 warps); warp owns 16 rows. Whole W staged in smem.
// ---------------------------------------------------------------------------
#define PROJ_SMEM ((64*XLD + 256*WLD) * 2)

__global__ __launch_bounds__(128) void proj_mma(
    const __nv_bfloat16* __restrict__ xb,
    const __nv_bfloat16* __restrict__ Wtb, const float* __restrict__ bt,
    const __nv_bfloat16* __restrict__ Wpb, const float* __restrict__ bp,
    const __nv_bfloat16* __restrict__ Wab, const float* __restrict__ ba,
    __nv_bfloat16* __restrict__ Qo, __nv_bfloat16* __restrict__ Ko,
    __nv_bfloat16* __restrict__ VTo)
{
    extern __shared__ __align__(16) __nv_bfloat16 psm[];
    __nv_bfloat16* xs = psm;               // 64 * XLD
    __nv_bfloat16* ws = psm + 64 * XLD;    // 256 * WLD

    const int z = blockIdx.z;
    const __nv_bfloat16* Wb = (z == 0) ? Wtb : (z == 1) ? Wpb : Wab;
    const float* bias = (z == 0) ? bt : (z == 1) ? bp : ba;

    const int tid  = threadIdx.x;
    const int warp = tid >> 5;
    const int lane = tid & 31;
    const int g    = lane >> 2;
    const int mq   = lane & 3;
    const int m0   = blockIdx.x * 64;
    const int r0   = warp * 16;

    // stage x tile [64][256] and W [256][128]
#pragma unroll
    for (int t = 0; t < 16; t++) {
        int e = (tid + t * 128) * 8;
        int r = e >> 8, d = e & 255;
        *(uint4*)&xs[r * XLD + d] = *(const uint4*)(xb + (size_t)(m0 + r) * CIN + d);
    }
#pragma unroll
    for (int t = 0; t < 32; t++) {
        int e = (tid + t * 128) * 8;
        int r = e >> 7, c = e & 127;
        *(uint4*)&ws[r * WLD + c] = *(const uint4*)(Wb + (size_t)r * C2 + c);
    }
    __syncthreads();

    // A-frags for 16 k-steps
    unsigned qa[16][4];
#pragma unroll
    for (int t = 0; t < 16; t++) {
        int k0 = t * 16;
        qa[t][0] = *(const unsigned*)&xs[(r0 + g    ) * XLD + k0 + 2 * mq];
        qa[t][1] = *(const unsigned*)&xs[(r0 + g + 8) * XLD + k0 + 2 * mq];
        qa[t][2] = *(const unsigned*)&xs[(r0 + g    ) * XLD + k0 + 8 + 2 * mq];
        qa[t][3] = *(const unsigned*)&xs[(r0 + g + 8) * XLD + k0 + 8 + 2 * mq];
    }

    float acc[16][4];
#pragma unroll
    for (int n = 0; n < 16; n++)
#pragma unroll
        for (int u = 0; u < 4; u++) acc[n][u] = 0.f;

    const unsigned ws_sa = (unsigned)__cvta_generic_to_shared(ws);
    // lane-invariant part of ldmatrix.trans address (W is n-contiguous)
    const unsigned laneW = 2 * (((lane & 7) + 8 * ((lane >> 3) & 1)) * WLD
                                + 8 * (lane >> 4));

#pragma unroll
    for (int t = 0; t < 16; t++) {
#pragma unroll
        for (int nq = 0; nq < 8; nq++) {
            unsigned b0, b1, b2, b3;
            ldsm4t(b0, b1, b2, b3, ws_sa + laneW + t * (32 * WLD) + nq * 32);
            mma16816(acc[2 * nq],     qa[t], b0, b1);
            mma16816(acc[2 * nq + 1], qa[t], b2, b3);
        }
    }

    // epilogue
#pragma unroll
    for (int n = 0; n < 16; n++) {
        int c0 = 8 * n + 2 * mq;
        float2 bv = *(const float2*)(bias + c0);
        float v0 = acc[n][0] + bv.x, v1 = acc[n][1] + bv.y;
        float v2 = acc[n][2] + bv.x, v3 = acc[n][3] + bv.y;
        int ra = m0 + r0 + g, rb = ra + 8;
        if (z < 2) {
            __nv_bfloat16* Crow = (z == 0) ? Qo : Ko;
            *(unsigned*)(Crow + (size_t)ra * C2 + c0) = pack_bf16x2(v0, v1);
            *(unsigned*)(Crow + (size_t)rb * C2 + c0) = pack_bf16x2(v2, v3);
        } else {
            VTo[(size_t)(c0    ) * NTOK + ra] = __float2bfloat16(v0);
            VTo[(size_t)(c0 + 1) * NTOK + ra] = __float2bfloat16(v1);
            VTo[(size_t)(c0    ) * NTOK + rb] = __float2bfloat16(v2);
            VTo[(size_t)(c0 + 1) * NTOK + rb] = __float2bfloat16(v3);
        }
    }
}

// ---------------------------------------------------------------------------
// Split-KV flash attention, bf16 mma + ldmatrix, fp32 accum.
// Grid (NTOK/TQ, NSPL). 128 threads (4 warps), warp owns 16 q rows.
// ---------------------------------------------------------------------------
#define ATTN_SMEM_ELEMS (TQ*ALD + 2*TK*ALD + 2*C2*VLD)
#define ATTN_SMEM_BYTES (ATTN_SMEM_ELEMS * 2)

__global__ __launch_bounds__(128) void attn_mma_kernel(
    const __nv_bfloat16* __restrict__ Qg,
    const __nv_bfloat16* __restrict__ Kg,
    const __nv_bfloat16* __restrict__ VTg,
    float* __restrict__ Oa,     // [NSPL][NTOK*C2]
    float* __restrict__ Ml)     // [NSPL][NTOK][2]
{
    extern __shared__ __align__(16) __nv_bfloat16 sm[];
    __nv_bfloat16* Qs  = sm;                    // TQ*ALD
    __nv_bfloat16* Ksm = Qs + TQ * ALD;         // 2 * TK*ALD
    __nv_bfloat16* Vsm = Ksm + 2 * TK * ALD;    // 2 * C2*VLD

    const int tid  = threadIdx.x;
    const int warp = tid >> 5;
    const int lane = tid & 31;
    const int g    = lane >> 2;
    const int mq   = lane & 3;
    const int q0   = blockIdx.x * TQ;
    const int spl  = blockIdx.y;
    const int kofs = spl * (NTOK / NSPL);
    const int r0   = warp * 16;

    // stage Q tile
#pragma unroll
    for (int t = 0; t < 8; t++) {
        int e = (tid + t * 128) * 8;
        int r = e >> 7, d = e & 127;
        *(uint4*)&Qs[r * ALD + d] = *(const uint4*)(Qg + (size_t)(q0 + r) * C2 + d);
    }

    // prefetch first KV tile into buffer 0
    {
        const size_t kb = (size_t)kofs;
#pragma unroll
        for (int t = 0; t < 8; t++) {
            int e = (tid + t * 128) * 8;
            int r = e >> 7, d = e & 127;
            cpasync16(&Ksm[r * ALD + d], Kg + (kb + r) * C2 + d);
        }
#pragma unroll
        for (int t = 0; t < 8; t++) {
            int e = (tid + t * 128) * 8;
            int r = e >> 6, d = e & 63;
            cpasync16(&Vsm[r * VLD + d], VTg + (size_t)r * NTOK + kb + d);
        }
        asm volatile("cp.async.commit_group;\n");
    }
    __syncthreads();

    // Q fragments
    unsigned qa[8][4];
#pragma unroll
    for (int t = 0; t < 8; t++) {
        int k0 = t * 16;
        qa[t][0] = *(const unsigned*)&Qs[(r0 + g    ) * ALD + k0 + 2 * mq];
        qa[t][1] = *(const unsigned*)&Qs[(r0 + g + 8) * ALD + k0 + 2 * mq];
        qa[t][2] = *(const unsigned*)&Qs[(r0 + g    ) * ALD + k0 + 8 + 2 * mq];
        qa[t][3] = *(const unsigned*)&Qs[(r0 + g + 8) * ALD + k0 + 8 + 2 * mq];
    }

    const unsigned ksm_sa = (unsigned)__cvta_generic_to_shared(Ksm);
    const unsigned vsm_sa = (unsigned)__cvta_generic_to_shared(Vsm);
    // lane-invariant ldmatrix offsets (non-trans: regs pack consecutive k)
    const unsigned laneK = 2 * ((lane & 7) * ALD + 8 * (lane >> 3));
    const unsigned laneV = 2 * ((((lane >> 4) * 8) + (lane & 7)) * VLD
                                + 8 * ((lane >> 3) & 1));

    float m0 = -INFINITY, m1 = -INFINITY, l0 = 0.f, l1 = 0.f;
    float o[16][4];
#pragma unroll
    for (int n = 0; n < 16; n++)
#pragma unroll
        for (int u = 0; u < 4; u++) o[n][u] = 0.f;

    const int NT = (NTOK / NSPL) / TK;   // 64 tiles
    for (int kt = 0; kt < NT; kt++) {
        const int cur = kt & 1;
        if (kt + 1 < NT) {
            __nv_bfloat16* kd = Ksm + (cur ^ 1) * TK * ALD;
            __nv_bfloat16* vd = Vsm + (cur ^ 1) * C2 * VLD;
            const size_t kb = (size_t)kofs + (size_t)(kt + 1) * TK;
#pragma unroll
            for (int t = 0; t < 8; t++) {
                int e = (tid + t * 128) * 8;
                int r = e >> 7, d = e & 127;
                cpasync16(&kd[r * ALD + d], Kg + (kb + r) * C2 + d);
            }
#pragma unroll
            for (int t = 0; t < 8; t++) {
                int e = (tid + t * 128) * 8;
                int r = e >> 6, d = e & 63;
                cpasync16(&vd[r * VLD + d], VTg + (size_t)r * NTOK + kb + d);
            }
            asm volatile("cp.async.commit_group;\n");
            asm volatile("cp.async.wait_group 1;\n");
        } else {
            asm volatile("cp.async.wait_group 0;\n");
        }
        __syncthreads();

        const unsigned kb_sa = ksm_sa + cur * (TK * ALD * 2);
        const unsigned vb_sa = vsm_sa + cur * (C2 * VLD * 2);

        // S = Q K^T : 8 n-tiles x 8 k-steps, B-frags via ldmatrix.x4
        float s[8][4];
#pragma unroll
        for (int j = 0; j < 8; j++) {
            s[j][0] = 0.f; s[j][1] = 0.f; s[j][2] = 0.f; s[j][3] = 0.f;
        }
#pragma unroll
        for (int j = 0; j < 8; j++) {
            unsigned rowb = kb_sa + laneK + j * (16 * ALD);   // 8 rows * ALD * 2B
#pragma unroll
            for (int tt = 0; tt < 4; tt++) {
                unsigned b0, b1, b2, b3;
                ldsm4(b0, b1, b2, b3, rowb + tt * 64);
                mma16816(s[j], qa[2 * tt],     b0, b1);
                mma16816(s[j], qa[2 * tt + 1], b2, b3);
            }
        }

        // online softmax
        float rmax0 = s[0][0], rmax1 = s[0][2];
#pragma unroll
        for (int j = 0; j < 8; j++) {
            rmax0 = fmaxf(rmax0, fmaxf(s[j][0], s[j][1]));
            rmax1 = fmaxf(rmax1, fmaxf(s[j][2], s[j][3]));
        }
        rmax0 = fmaxf(rmax0, __shfl_xor_sync(0xffffffffu, rmax0, 1));
        rmax0 = fmaxf(rmax0, __shfl_xor_sync(0xffffffffu, rmax0, 2));
        rmax1 = fmaxf(rmax1, __shfl_xor_sync(0xffffffffu, rmax1, 1));
        rmax1 = fmaxf(rmax1, __shfl_xor_sync(0xffffffffu, rmax1, 2));

        float mn0 = fmaxf(m0, rmax0), mn1 = fmaxf(m1, rmax1);
        float sc0 = __expf(m0 - mn0), sc1 = __expf(m1 - mn1);
        m0 = mn0; m1 = mn1;

        float rs0 = 0.f, rs1 = 0.f;
#pragma unroll
        for (int j = 0; j < 8; j++) {
            s[j][0] = __expf(s[j][0] - mn0); rs0 += s[j][0];
            s[j][1] = __expf(s[j][1] - mn0); rs0 += s[j][1];
            s[j][2] = __expf(s[j][2] - mn1); rs1 += s[j][2];
            s[j][3] = __expf(s[j][3] - mn1); rs1 += s[j][3];
        }
        rs0 += __shfl_xor_sync(0xffffffffu, rs0, 1);
        rs0 += __shfl_xor_sync(0xffffffffu, rs0, 2);
        rs1 += __shfl_xor_sync(0xffffffffu, rs1, 1);
        rs1 += __shfl_xor_sync(0xffffffffu, rs1, 2);
        l0 = l0 * sc0 + rs0;
        l1 = l1 * sc1 + rs1;
#pragma unroll
        for (int n = 0; n < 16; n++) {
            o[n][0] *= sc0; o[n][1] *= sc0;
            o[n][2] *= sc1; o[n][3] *= sc1;
        }

        // O += P @ V : B-frags via ldmatrix.x4 from V^T layout
#pragma unroll
        for (int t = 0; t < 4; t++) {
            unsigned pa[4];
            pa[0] = pack_bf16x2(s[2*t  ][0], s[2*t  ][1]);
            pa[1] = pack_bf16x2(s[2*t  ][2], s[2*t  ][3]);
            pa[2] = pack_bf16x2(s[2*t+1][0], s[2*t+1][1]);
            pa[3] = pack_bf16x2(s[2*t+1][2], s[2*t+1][3]);
#pragma unroll
            for (int nq = 0; nq < 8; nq++) {
                unsigned b0, b1, b2, b3;
                ldsm4(b0, b1, b2, b3, vb_sa + laneV + nq * (32 * VLD) + t * 32);
                mma16816(o[2 * nq],     pa, b0, b1);
                mma16816(o[2 * nq + 1], pa, b2, b3);
            }
        }
        __syncthreads();
    }

    // store unnormalized O + (m, l)
    float* Op = Oa + (size_t)spl * NTOK * C2;
#pragma unroll
    for (int n = 0; n < 16; n++) {
        int c = 8 * n + 2 * mq;
        *(float2*)(Op + (size_t)(q0 + r0 + g    ) * C2 + c) = make_float2(o[n][0], o[n][1]);
        *(float2*)(Op + (size_t)(q0 + r0 + g + 8) * C2 + c) = make_float2(o[n][2], o[n][3]);
    }
    if (mq == 0) {
        float* mlp = Ml + (size_t)spl * NTOK * 2;
        *(float2*)(mlp + (size_t)(q0 + r0 + g    ) * 2) = make_float2(m0, l0);
        *(float2*)(mlp + (size_t)(q0 + r0 + g + 8) * 2) = make_float2(m1, l1);
    }
}

// ---------------------------------------------------------------------------
// Merge split-KV partials -> normalized attention output, bf16.
// ---------------------------------------------------------------------------
__global__ __launch_bounds__(256) void attn_merge(
    const float* __restrict__ Oa, const float* __restrict__ Ml,
    __nv_bfloat16* __restrict__ Outb)
{
    const int tid = blockIdx.x * 256 + threadIdx.x;   // 32768 threads
#pragma unroll
    for (int t = 0; t < 8; t++) {
        int idx = (tid + t * 32768) * 4;
        int row = idx >> 7;
        float2 ml1 = *(const float2*)(Ml + (size_t)row * 2);
        float2 ml2 = *(const float2*)(Ml + (size_t)(NTOK + row) * 2);
        float mm = fmaxf(ml1.x, ml2.x);
        float w1 = __expf(ml1.x - mm);
        float w2 = __expf(ml2.x - mm);
        float inv = 1.f / (w1 * ml1.y + w2 * ml2.y);
        w1 *= inv; w2 *= inv;
        float4 o1 = *(const float4*)(Oa + idx);
        float4 o2 = *(const float4*)(Oa + (size_t)NTOK * C2 + idx);
        uint2 u;
        u.x = pack_bf16x2(o1.x * w1 + o2.x * w2, o1.y * w1 + o2.y * w2);
        u.y = pack_bf16x2(o1.z * w1 + o2.z * w2, o1.w * w1 + o2.w * w2);
        *(uint2*)(Outb + idx) = u;
    }
}

// ---------------------------------------------------------------------------
// Dense gate (unchanged): split-K partials -> reduce -> softmax.
// ---------------------------------------------------------------------------
__global__ __launch_bounds__(256) void dense_partial(
    const float* __restrict__ x, const float* __restrict__ Wd,
    float* __restrict__ part)
{
    __shared__ __align__(16) float xs[BATCH * KCHUNK];
    const int tid = threadIdx.x;
    const int k0  = blockIdx.x * KCHUNK;

#pragma unroll
    for (int t = 0; t < 2; t++) {
        int e  = (tid + t * 256) * 4;
        int b  = e >> 8;
        int kk = e & 255;
        *(float4*)&xs[b * KCHUNK + kk] =
            *(const float4*)(x + (size_t)b * KDENSE + k0 + kk);
    }
    __syncthreads();

    float4 acc[BATCH];
#pragma unroll
    for (int b = 0; b < BATCH; b++) acc[b] = make_float4(0.f, 0.f, 0.f, 0.f);

    const int j = tid * 4;
#pragma unroll 4
    for (int kk = 0; kk < KCHUNK; kk++) {
        float4 w = *(const float4*)(Wd + (size_t)(k0 + kk) * HWPOS + j);
#pragma unroll
        for (int b = 0; b < BATCH; b++) {
            float xv = xs[b * KCHUNK + kk];
            acc[b].x += xv * w.x; acc[b].y += xv * w.y;
            acc[b].z += xv * w.z; acc[b].w += xv * w.w;
        }
    }
#pragma unroll
    for (int b = 0; b < BATCH; b++)
        *(float4*)&part[((size_t)blockIdx.x * BATCH + b) * HWPOS + j] = acc[b];
}

__global__ __launch_bounds__(256) void dense_reduce(
    const float* __restrict__ part, float* __restrict__ part2)
{
    const int b   = blockIdx.x & 7;
    const int grp = blockIdx.x >> 3;
    const int j   = threadIdx.x * 4;
    float4 s = make_float4(0.f, 0.f, 0.f, 0.f);
    for (int c = 0; c < KCH / NGRP; c++) {
        int kc = grp * (KCH / NGRP) + c;
        float4 p = *(const float4*)(part + ((size_t)kc * BATCH + b) * HWPOS + j);
        s.x += p.x; s.y += p.y; s.z += p.z; s.w += p.w;
    }
    *(float4*)(part2 + ((size_t)grp * BATCH + b) * HWPOS + j) = s;
}

__global__ __launch_bounds__(256) void dense_softmax(
    const float* __restrict__ part2, const float* __restrict__ bias,
    float* __restrict__ sp)
{
    __shared__ float red[256];
    const int b   = blockIdx.x;
    const int tid = threadIdx.x;
    const int j   = tid * 4;

    float4 s = *(const float4*)(bias + j);
    for (int grp = 0; grp < NGRP; grp++) {
        float4 p = *(const float4*)(part2 + ((size_t)grp * BATCH + b) * HWPOS + j);
        s.x += p.x; s.y += p.y; s.z += p.z; s.w += p.w;
    }

    float lm = fmaxf(fmaxf(s.x, s.y), fmaxf(s.z, s.w));
    red[tid] = lm;
    __syncthreads();
    for (int off = 128; off > 0; off >>= 1) {
        if (tid < off) red[tid] = fmaxf(red[tid], red[tid + off]);
        __syncthreads();
    }
    float mx = red[0];
    __syncthreads();

    float4 e;
    e.x = __expf(s.x - mx); e.y = __expf(s.y - mx);
    e.z = __expf(s.z - mx); e.w = __expf(s.w - mx);
    red[tid] = e.x + e.y + e.z + e.w;
    __syncthreads();
    for (int off = 128; off > 0; off >>= 1) {
        if (tid < off) red[tid] += red[tid + off];
        __syncthreads();
    }
    float inv = 1.f / red[0];
    e.x *= inv; e.y *= inv; e.z *= inv; e.w *= inv;
    *(float4*)(sp + (size_t)b * HWPOS + j) = e;
}

// ---------------------------------------------------------------------------
// Tensor-core mask GEMM + fused epilogue: out = (attnb @ Wmb)*sp[row] + x.
// Grid (128 m-tiles, 2 n-halves), 128 threads (4 warps, 16 rows each).
// ---------------------------------------------------------------------------
#define MASK_SMEM ((64*WLD + 128*WLD) * 2)

__global__ __launch_bounds__(128) void mask_mma(
    const __nv_bfloat16* __restrict__ Ab,    // [8192][128]
    const __nv_bfloat16* __restrict__ Wmb,   // [128][256]
    float* __restrict__ C,
    const float* __restrict__ sp, const float* __restrict__ xres)
{
    extern __shared__ __align__(16) __nv_bfloat16 msm[];
    __nv_bfloat16* as = msm;               // 64 * WLD
    __nv_bfloat16* wm = msm + 64 * WLD;    // 128 * WLD

    const int tid  = threadIdx.x;
    const int warp = tid >> 5;
    const int lane = tid & 31;
    const int g    = lane >> 2;
    const int mq   = lane & 3;
    const int m0   = blockIdx.x * 64;
    const int col0 = blockIdx.y * 128;
    const int r0   = warp * 16;

#pragma unroll
    for (int t = 0; t < 8; t++) {
        int e = (tid + t * 128) * 8;
        int r = e >> 7, d = e & 127;
        *(uint4*)&as[r * WLD + d] = *(const uint4*)(Ab + (size_t)(m0 + r) * C2 + d);
    }
#pragma unroll
    for (int t = 0; t < 16; t++) {
        int e = (tid + t * 128) * 8;
        int r = e >> 7, c = e & 127;
        *(uint4*)&wm[r * WLD + c] = *(const uint4*)(Wmb + (size_t)r * CIN + col0 + c);
    }
    __syncthreads();

    unsigned qa[8][4];
#pragma unroll
    for (int t = 0; t < 8; t++) {
        int k0 = t * 16;
        qa[t][0] = *(const unsigned*)&as[(r0 + g    ) * WLD + k0 + 2 * mq];
        qa[t][1] = *(const unsigned*)&as[(r0 + g + 8) * WLD + k0 + 2 * mq];
        qa[t][2] = *(const unsigned*)&as[(r0 + g    ) * WLD + k0 + 8 + 2 * mq];
        qa[t][3] = *(const unsigned*)&as[(r0 + g + 8) * WLD + k0 + 8 + 2 * mq];
    }

    float acc[16][4];
#pragma unroll
    for (int n = 0; n < 16; n++)
#pragma unroll
        for (int u = 0; u < 4; u++) acc[n][u] = 0.f;

    const unsigned wm_sa = (unsigned)__cvta_generic_to_shared(wm);
    const unsigned laneW = 2 * (((lane & 7) + 8 * ((lane >> 3) & 1)) * WLD
                                + 8 * (lane >> 4));

#pragma unroll
    for (int t = 0; t < 8; t++) {
#pragma unroll
        for (int nq = 0; nq < 8; nq++) {
            unsigned b0, b1, b2, b3;
            ldsm4t(b0, b1, b2, b3, wm_sa + laneW + t * (32 * WLD) + nq * 32);
            mma16816(acc[2 * nq],     qa[t], b0, b1);
            mma16816(acc[2 * nq + 1], qa[t], b2, b3);
        }
    }

    const int ra = m0 + r0 + g, rb = ra + 8;
    const float spa = sp[ra], spb = sp[rb];
#pragma unroll
    for (int n = 0; n < 16; n++) {
        int c0 = col0 + 8 * n + 2 * mq;
        float2 xa = *(const float2*)(xres + (size_t)ra * CIN + c0);
        float2 xb2 = *(const float2*)(xres + (size_t)rb * CIN + c0);
        float2 va = make_float2(acc[n][0] * spa + xa.x, acc[n][1] * spa + xa.y);
        float2 vb = make_float2(acc[n][2] * spb + xb2.x, acc[n][3] * spb + xb2.y);
        *(float2*)(C + (size_t)ra * CIN + c0) = va;
        *(float2*)(C + (size_t)rb * CIN + c0) = vb;
    }
}

// ---------------------------------------------------------------------------
// Launcher with fork-join stream overlap.
// ---------------------------------------------------------------------------
static cudaStream_t s_aux = nullptr;
static cudaEvent_t  s_evFork = nullptr, s_evJoin = nullptr;

extern "C" void kernel_launch(void* const* d_in, const int* in_sizes, int n_in,
                              void* d_out, int out_size)
{
    (void)in_sizes; (void)n_in; (void)out_size;
    const float* x       = (const float*)d_in[0];
    const float* W_theta = (const float*)d_in[1];
    const float* b_theta = (const float*)d_in[2];
    const float* W_phi   = (const float*)d_in[3];
    const float* b_phi   = (const float*)d_in[4];
    const float* W_alpha = (const float*)d_in[5];
    const float* b_alpha = (const float*)d_in[6];
    const float* W_mask  = (const float*)d_in[7];
    const float* W_dense = (const float*)d_in[8];
    const float* b_dense = (const float*)d_in[9];
    float* out = (float*)d_out;

    if (!s_aux) {
        cudaStreamCreateWithFlags(&s_aux, cudaStreamNonBlocking);
        cudaEventCreateWithFlags(&s_evFork, cudaEventDisableTiming);
        cudaEventCreateWithFlags(&s_evJoin, cudaEventDisableTiming);
    }

    __nv_bfloat16 *xb, *wtb, *wpb, *wab, *wmb, *q, *k, *vT, *attnb;
    float *oa, *ml, *part, *part2, *sp;
    cudaGetSymbolAddress((void**)&xb,    g_xb);
    cudaGetSymbolAddress((void**)&wtb,   g_wtb);
    cudaGetSymbolAddress((void**)&wpb,   g_wpb);
    cudaGetSymbolAddress((void**)&wab,   g_wab);
    cudaGetSymbolAddress((void**)&wmb,   g_wmb);
    cudaGetSymbolAddress((void**)&q,     g_q);
    cudaGetSymbolAddress((void**)&k,     g_k);
    cudaGetSymbolAddress((void**)&vT,    g_vT);
    cudaGetSymbolAddress((void**)&oa,    g_oa);
    cudaGetSymbolAddress((void**)&ml,    g_ml);
    cudaGetSymbolAddress((void**)&attnb, g_attnb);
    cudaGetSymbolAddress((void**)&part,  g_part);
    cudaGetSymbolAddress((void**)&part2, g_part2);
    cudaGetSymbolAddress((void**)&sp,    g_sp);

    cudaFuncSetAttribute(attn_mma_kernel,
                         cudaFuncAttributeMaxDynamicSharedMemorySize,
                         ATTN_SMEM_BYTES);
    cudaFuncSetAttribute(proj_mma,
                         cudaFuncAttributeMaxDynamicSharedMemorySize,
                         PROJ_SMEM);
    cudaFuncSetAttribute(mask_mma,
                         cudaFuncAttributeMaxDynamicSharedMemorySize,
                         MASK_SMEM);

    // ---- fork: dense chain on auxiliary stream ----
    cudaEventRecord(s_evFork, 0);
    cudaStreamWaitEvent(s_aux, s_evFork, 0);
    dense_partial<<<KCH, 256, 0, s_aux>>>(x, W_dense, part);
    dense_reduce<<<NGRP * BATCH, 256, 0, s_aux>>>(part, part2);
    dense_softmax<<<BATCH, 256, 0, s_aux>>>(part2, b_dense, sp);
    cudaEventRecord(s_evJoin, s_aux);

    // ---- main chain ----
    conv_x<<<NTOK * CIN / (256 * 8), 256>>>(x, xb);
    conv_w<<<(4 * CIN * C2) / (256 * 8), 256>>>(W_theta, W_phi, W_alpha, W_mask,
                                                wtb, wpb, wab, wmb);
    proj_mma<<<dim3(128, 1, 3), 128, PROJ_SMEM>>>(xb, wtb, b_theta, wpb, b_phi,
                                                  wab, b_alpha, q, k, vT);
    attn_mma_kernel<<<dim3(NTOK / TQ, NSPL), 128, ATTN_SMEM_BYTES>>>(
        q, k, vT, oa, ml);
    attn_merge<<<128, 256>>>(oa, ml, attnb);

    // ---- join, then fused mask GEMM + gate + residual ----
    cudaStreamWaitEvent(0, s_evJoin, 0);
    mask_mma<<<dim3(128, 2), 128, MASK_SMEM>>>(attnb, wmb, out, sp, x);
}

// round 14
// speedup vs baseline: 6.7120x; 1.3830x over previous
#include <cuda_runtime.h>
#include <cuda_bf16.h>
#include <math.h>

// ---------------------------------------------------------------------------
// Problem constants
// ---------------------------------------------------------------------------
#define NTOK   8192
#define CIN    256
#define C2     128
#define HWPOS  1024
#define BATCH  8
#define KDENSE (HWPOS*CIN)     // 262144

// Dense gate (tensor-core split-K)
#define DNCH   64              // k-chunks
#define DKC    (KDENSE/DNCH)   // 4096 k per chunk
#define LDW    132             // smem fp32 row stride (128 + 4 pad)

// Attention tiling
#define TQ    64               // q rows per block
#define TK    32               // keys per KV tile
#define NSPL  4                // KV splits
#define ALD   136              // smem stride, 128-wide bf16 rows
#define VLD   40               // smem stride, 32-wide bf16 rows (+8 pad)

// proj / mask tiling
#define XLD   264              // x-tile row stride (bf16), 256-wide (+8 pad)
#define WLD   136              // weight smem row stride (bf16), 128-wide (+8)

// ---------------------------------------------------------------------------
// Scratch (static device arrays; no allocation anywhere)
// ---------------------------------------------------------------------------
__device__ __nv_bfloat16 g_xb [NTOK * CIN];    // x in bf16
__device__ __nv_bfloat16 g_wtb[CIN * C2];
__device__ __nv_bfloat16 g_wpb[CIN * C2];
__device__ __nv_bfloat16 g_wab[CIN * C2];
__device__ __nv_bfloat16 g_wmb[C2 * CIN];      // W_mask bf16
__device__ __nv_bfloat16 g_q  [NTOK * C2];
__device__ __nv_bfloat16 g_k  [NTOK * C2];
__device__ __nv_bfloat16 g_vT [C2 * NTOK];
__device__ float g_oa  [NSPL][NTOK * C2];      // unnormalized partial O
__device__ float g_ml  [NSPL][NTOK][2];        // per-row (m, l)
__device__ __nv_bfloat16 g_attnb[NTOK * C2];   // merged attention, bf16
__device__ float g_part [DNCH * BATCH * HWPOS];
__device__ float g_sp   [BATCH * HWPOS];

// ---------------------------------------------------------------------------
// Helpers
// ---------------------------------------------------------------------------
__device__ __forceinline__ void mma16816(float* c, const unsigned* a,
                                         unsigned b0, unsigned b1) {
    asm volatile(
        "mma.sync.aligned.m16n8k16.row.col.f32.bf16.bf16.f32 "
        "{%0,%1,%2,%3}, {%4,%5,%6,%7}, {%8,%9}, {%0,%1,%2,%3};\n"
        : "+f"(c[0]), "+f"(c[1]), "+f"(c[2]), "+f"(c[3])
        : "r"(a[0]), "r"(a[1]), "r"(a[2]), "r"(a[3]), "r"(b0), "r"(b1));
}
__device__ __forceinline__ void ldsm4(unsigned& r0, unsigned& r1,
                                      unsigned& r2, unsigned& r3, unsigned a) {
    asm volatile("ldmatrix.sync.aligned.m8n8.x4.shared.b16 {%0,%1,%2,%3}, [%4];"
                 : "=r"(r0), "=r"(r1), "=r"(r2), "=r"(r3) : "r"(a));
}
__device__ __forceinline__ void ldsm4t(unsigned& r0, unsigned& r1,
                                       unsigned& r2, unsigned& r3, unsigned a) {
    asm volatile("ldmatrix.sync.aligned.m8n8.x4.trans.shared.b16 {%0,%1,%2,%3}, [%4];"
                 : "=r"(r0), "=r"(r1), "=r"(r2), "=r"(r3) : "r"(a));
}
__device__ __forceinline__ void cpasync16(void* s, const void* g) {
    unsigned sa = (unsigned)__cvta_generic_to_shared(s);
    asm volatile("cp.async.cg.shared.global [%0], [%1], 16;\n"
                 :: "r"(sa), "l"(g));
}
__device__ __forceinline__ unsigned pack_bf16x2(float lo, float hi) {
    __nv_bfloat162 h = __float22bfloat162_rn(make_float2(lo, hi));
    return *(unsigned*)&h;
}

// ---------------------------------------------------------------------------
// fp32 -> bf16 conversions
// ---------------------------------------------------------------------------
__global__ __launch_bounds__(256) void conv_x(
    const float* __restrict__ x, __nv_bfloat16* __restrict__ xb)
{
    int i = (blockIdx.x * 256 + threadIdx.x) * 8;
    float4 a = *(const float4*)(x + i);
    float4 b = *(const float4*)(x + i + 4);
    uint4 u;
    u.x = pack_bf16x2(a.x, a.y); u.y = pack_bf16x2(a.z, a.w);
    u.z = pack_bf16x2(b.x, b.y); u.w = pack_bf16x2(b.z, b.w);
    *(uint4*)(xb + i) = u;
}

__global__ __launch_bounds__(256) void conv_w(
    const float* __restrict__ Wt, const float* __restrict__ Wp,
    const float* __restrict__ Wa, const float* __restrict__ Wm,
    __nv_bfloat16* __restrict__ Wtb, __nv_bfloat16* __restrict__ Wpb,
    __nv_bfloat16* __restrict__ Wab, __nv_bfloat16* __restrict__ Wmb)
{
    int i = (blockIdx.x * 256 + threadIdx.x) * 8;
    int seg = i >> 15;
    int off = i & 32767;
    const float* src = (seg == 0) ? Wt : (seg == 1) ? Wp : (seg == 2) ? Wa : Wm;
    __nv_bfloat16* dst = (seg == 0) ? Wtb : (seg == 1) ? Wpb : (seg == 2) ? Wab : Wmb;
    float4 a = *(const float4*)(src + off);
    float4 b = *(const float4*)(src + off + 4);
    uint4 u;
    u.x = pack_bf16x2(a.x, a.y); u.y = pack_bf16x2(a.z, a.w);
    u.z = pack_bf16x2(b.x, b.y); u.w = pack_bf16x2(b.z, b.w);
    *(uint4*)(dst + off) = u;
}

// ---------------------------------------------------------------------------
// Dense gate, tensor-core split-K:
// part[kc][b][1024] = xb[b, kc*4096:(kc+1)*4096] @ Wd[same rows][1024 cols].
// Grid (8 col-tiles of 128, 64 k-chunks). Block = 128 threads (4 warps, each
// owns 32 cols). W_dense staged fp32 via cp.async (32-row stages, double
// buffered), converted to bf16 in registers at mma time. M=16 (8 batch + 8
// zero-pad rows as constant-zero A-frags).
// ---------------------------------------------------------------------------
__global__ __launch_bounds__(128) void dense_mma(
    const __nv_bfloat16* __restrict__ xb, const float* __restrict__ Wd,
    float* __restrict__ part)
{
    __shared__ __align__(16) float ws[2][32][LDW];

    const int tid  = threadIdx.x;
    const int warp = tid >> 5;
    const int lane = tid & 31;
    const int g    = lane >> 2;     // A row (batch) / B col / C row
    const int mq   = lane & 3;      // k pair index
    const int col0 = blockIdx.x * 128;
    const int kc   = blockIdx.y;
    const int kbase = kc * DKC;

    const int colw = warp * 32;

    float acc[4][4];
#pragma unroll
    for (int n = 0; n < 4; n++)
#pragma unroll
        for (int u = 0; u < 4; u++) acc[n][u] = 0.f;

    // prologue: stage 0
    {
#pragma unroll
        for (int t = 0; t < 8; t++) {
            int e = tid + t * 128;            // 0..1023
            int r = e >> 5, c = (e & 31) * 4;
            cpasync16(&ws[0][r][c], Wd + (size_t)(kbase + r) * HWPOS + col0 + c);
        }
        asm volatile("cp.async.commit_group;\n");
    }

    const int NSTAGE = DKC / 32;    // 128
    for (int s = 0; s < NSTAGE; s++) {
        const int cur = s & 1;
        if (s + 1 < NSTAGE) {
            const int k0 = kbase + (s + 1) * 32;
#pragma unroll
            for (int t = 0; t < 8; t++) {
                int e = tid + t * 128;
                int r = e >> 5, c = (e & 31) * 4;
                cpasync16(&ws[cur ^ 1][r][c],
                          Wd + (size_t)(k0 + r) * HWPOS + col0 + c);
            }
            asm volatile("cp.async.commit_group;\n");
            asm volatile("cp.async.wait_group 1;\n");
        } else {
            asm volatile("cp.async.wait_group 0;\n");
        }
        __syncthreads();

#pragma unroll
        for (int step = 0; step < 2; step++) {
            const int kk = step * 16;
            const size_t kglob = (size_t)kbase + s * 32 + kk;
            unsigned a[4];
            a[0] = *(const unsigned*)(xb + (size_t)g * KDENSE + kglob + 2 * mq);
            a[1] = 0u;
            a[2] = *(const unsigned*)(xb + (size_t)g * KDENSE + kglob + 8 + 2 * mq);
            a[3] = 0u;
#pragma unroll
            for (int nt = 0; nt < 4; nt++) {
                const int c = colw + nt * 8 + g;
                unsigned b0 = pack_bf16x2(ws[cur][kk + 2 * mq][c],
                                          ws[cur][kk + 2 * mq + 1][c]);
                unsigned b1 = pack_bf16x2(ws[cur][kk + 2 * mq + 8][c],
                                          ws[cur][kk + 2 * mq + 9][c]);
                mma16816(acc[nt], a, b0, b1);
            }
        }
        __syncthreads();
    }

    // epilogue: rows 0..7 (batch) only; c0,c1 = (row g, cols 2mq,2mq+1)
#pragma unroll
    for (int nt = 0; nt < 4; nt++) {
        int c = col0 + colw + nt * 8 + 2 * mq;
        *(float2*)(part + ((size_t)kc * BATCH + g) * HWPOS + c) =
            make_float2(acc[nt][0], acc[nt][1]);
    }
}

// ---------------------------------------------------------------------------
// Dense gate: deterministic reduce over 64 chunks + bias + softmax. Grid = 8.
// ---------------------------------------------------------------------------
__global__ __launch_bounds__(256) void dense_softmax(
    const float* __restrict__ part, const float* __restrict__ bias,
    float* __restrict__ sp)
{
    __shared__ float red[256];
    const int b   = blockIdx.x;
    const int tid = threadIdx.x;
    const int j   = tid * 4;

    float4 s = *(const float4*)(bias + j);
    for (int kc = 0; kc < DNCH; kc++) {
        float4 p = *(const float4*)(part + ((size_t)kc * BATCH + b) * HWPOS + j);
        s.x += p.x; s.y += p.y; s.z += p.z; s.w += p.w;
    }

    float lm = fmaxf(fmaxf(s.x, s.y), fmaxf(s.z, s.w));
    red[tid] = lm;
    __syncthreads();
    for (int off = 128; off > 0; off >>= 1) {
        if (tid < off) red[tid] = fmaxf(red[tid], red[tid + off]);
        __syncthreads();
    }
    float mx = red[0];
    __syncthreads();

    float4 e;
    e.x = __expf(s.x - mx); e.y = __expf(s.y - mx);
    e.z = __expf(s.z - mx); e.w = __expf(s.w - mx);
    red[tid] = e.x + e.y + e.z + e.w;
    __syncthreads();
    for (int off = 128; off > 0; off >>= 1) {
        if (tid < off) red[tid] += red[tid + off];
        __syncthreads();
    }
    float inv = 1.f / red[0];
    e.x *= inv; e.y *= inv; e.z *= inv; e.w *= inv;
    *(float4*)(sp + (size_t)b * HWPOS + j) = e;
}

// ---------------------------------------------------------------------------
// Tensor-core projections (unchanged from R12).
// ---------------------------------------------------------------------------
#define PROJ_SMEM ((64*XLD + 256*WLD) * 2)

__global__ __launch_bounds__(128) void proj_mma(
    const __nv_bfloat16* __restrict__ xb,
    const __nv_bfloat16* __restrict__ Wtb, const float* __restrict__ bt,
    const __nv_bfloat16* __restrict__ Wpb, const float* __restrict__ bp,
    const __nv_bfloat16* __restrict__ Wab, const float* __restrict__ ba,
    __nv_bfloat16* __restrict__ Qo, __nv_bfloat16* __restrict__ Ko,
    __nv_bfloat16* __restrict__ VTo)
{
    extern __shared__ __align__(16) __nv_bfloat16 psm[];
    __nv_bfloat16* xs = psm;               // 64 * XLD
    __nv_bfloat16* ws = psm + 64 * XLD;    // 256 * WLD

    const int z = blockIdx.z;
    const __nv_bfloat16* Wb = (z == 0) ? Wtb : (z == 1) ? Wpb : Wab;
    const float* bias = (z == 0) ? bt : (z == 1) ? bp : ba;

    const int tid  = threadIdx.x;
    const int warp = tid >> 5;
    const int lane = tid & 31;
    const int g    = lane >> 2;
    const int mq   = lane & 3;
    const int m0   = blockIdx.x * 64;
    const int r0   = warp * 16;

#pragma unroll
    for (int t = 0; t < 16; t++) {
        int e = (tid + t * 128) * 8;
        int r = e >> 8, d = e & 255;
        *(uint4*)&xs[r * XLD + d] = *(const uint4*)(xb + (size_t)(m0 + r) * CIN + d);
    }
#pragma unroll
    for (int t = 0; t < 32; t++) {
        int e = (tid + t * 128) * 8;
        int r = e >> 7, c = e & 127;
        *(uint4*)&ws[r * WLD + c] = *(const uint4*)(Wb + (size_t)r * C2 + c);
    }
    __syncthreads();

    unsigned qa[16][4];
#pragma unroll
    for (int t = 0; t < 16; t++) {
        int k0 = t * 16;
        qa[t][0] = *(const unsigned*)&xs[(r0 + g    ) * XLD + k0 + 2 * mq];
        qa[t][1] = *(const unsigned*)&xs[(r0 + g + 8) * XLD + k0 + 2 * mq];
        qa[t][2] = *(const unsigned*)&xs[(r0 + g    ) * XLD + k0 + 8 + 2 * mq];
        qa[t][3] = *(const unsigned*)&xs[(r0 + g + 8) * XLD + k0 + 8 + 2 * mq];
    }

    float acc[16][4];
#pragma unroll
    for (int n = 0; n < 16; n++)
#pragma unroll
        for (int u = 0; u < 4; u++) acc[n][u] = 0.f;

    const unsigned ws_sa = (unsigned)__cvta_generic_to_shared(ws);
    const unsigned laneW = 2 * (((lane & 7) + 8 * ((lane >> 3) & 1)) * WLD
                                + 8 * (lane >> 4));

#pragma unroll
    for (int t = 0; t < 16; t++) {
#pragma unroll
        for (int nq = 0; nq < 8; nq++) {
            unsigned b0, b1, b2, b3;
            ldsm4t(b0, b1, b2, b3, ws_sa + laneW + t * (32 * WLD) + nq * 32);
            mma16816(acc[2 * nq],     qa[t], b0, b1);
            mma16816(acc[2 * nq + 1], qa[t], b2, b3);
        }
    }

#pragma unroll
    for (int n = 0; n < 16; n++) {
        int c0 = 8 * n + 2 * mq;
        float2 bv = *(const float2*)(bias + c0);
        float v0 = acc[n][0] + bv.x, v1 = acc[n][1] + bv.y;
        float v2 = acc[n][2] + bv.x, v3 = acc[n][3] + bv.y;
        int ra = m0 + r0 + g, rb = ra + 8;
        if (z < 2) {
            __nv_bfloat16* Crow = (z == 0) ? Qo : Ko;
            *(unsigned*)(Crow + (size_t)ra * C2 + c0) = pack_bf16x2(v0, v1);
            *(unsigned*)(Crow + (size_t)rb * C2 + c0) = pack_bf16x2(v2, v3);
        } else {
            VTo[(size_t)(c0    ) * NTOK + ra] = __float2bfloat16(v0);
            VTo[(size_t)(c0 + 1) * NTOK + ra] = __float2bfloat16(v1);
            VTo[(size_t)(c0    ) * NTOK + rb] = __float2bfloat16(v2);
            VTo[(size_t)(c0 + 1) * NTOK + rb] = __float2bfloat16(v3);
        }
    }
}

// ---------------------------------------------------------------------------
// Split-KV flash attention, bf16 mma + ldmatrix, fp32 accum.
// Grid (128, NSPL=4). 128 threads (4 warps). TK=32, double-buffered cp.async.
// Smem ~54KB -> 3-4 blocks/SM.
// ---------------------------------------------------------------------------
#define ATTN_SMEM_ELEMS (TQ*ALD + 2*TK*ALD + 2*C2*VLD)
#define ATTN_SMEM_BYTES (ATTN_SMEM_ELEMS * 2)

__global__ __launch_bounds__(128) void attn_mma_kernel(
    const __nv_bfloat16* __restrict__ Qg,
    const __nv_bfloat16* __restrict__ Kg,
    const __nv_bfloat16* __restrict__ VTg,
    float* __restrict__ Oa,     // [NSPL][NTOK*C2]
    float* __restrict__ Ml)     // [NSPL][NTOK][2]
{
    extern __shared__ __align__(16) __nv_bfloat16 sm[];
    __nv_bfloat16* Qs  = sm;                    // TQ*ALD
    __nv_bfloat16* Ksm = Qs + TQ * ALD;         // 2 * TK*ALD
    __nv_bfloat16* Vsm = Ksm + 2 * TK * ALD;    // 2 * C2*VLD

    const int tid  = threadIdx.x;
    const int warp = tid >> 5;
    const int lane = tid & 31;
    const int g    = lane >> 2;
    const int mq   = lane & 3;
    const int q0   = blockIdx.x * TQ;
    const int spl  = blockIdx.y;
    const int kofs = spl * (NTOK / NSPL);
    const int r0   = warp * 16;

    // stage Q tile
#pragma unroll
    for (int t = 0; t < 8; t++) {
        int e = (tid + t * 128) * 8;
        int r = e >> 7, d = e & 127;
        *(uint4*)&Qs[r * ALD + d] = *(const uint4*)(Qg + (size_t)(q0 + r) * C2 + d);
    }

    // prefetch first KV tile
    {
        const size_t kb = (size_t)kofs;
#pragma unroll
        for (int t = 0; t < 4; t++) {
            int e = (tid + t * 128) * 8;
            int r = e >> 7, d = e & 127;
            cpasync16(&Ksm[r * ALD + d], Kg + (kb + r) * C2 + d);
        }
#pragma unroll
        for (int t = 0; t < 4; t++) {
            int e = (tid + t * 128) * 8;
            int r = e >> 5, d = e & 31;
            cpasync16(&Vsm[r * VLD + d], VTg + (size_t)r * NTOK + kb + d);
        }
        asm volatile("cp.async.commit_group;\n");
    }
    __syncthreads();

    unsigned qa[8][4];
#pragma unroll
    for (int t = 0; t < 8; t++) {
        int k0 = t * 16;
        qa[t][0] = *(const unsigned*)&Qs[(r0 + g    ) * ALD + k0 + 2 * mq];
        qa[t][1] = *(const unsigned*)&Qs[(r0 + g + 8) * ALD + k0 + 2 * mq];
        qa[t][2] = *(const unsigned*)&Qs[(r0 + g    ) * ALD + k0 + 8 + 2 * mq];
        qa[t][3] = *(const unsigned*)&Qs[(r0 + g + 8) * ALD + k0 + 8 + 2 * mq];
    }

    const unsigned ksm_sa = (unsigned)__cvta_generic_to_shared(Ksm);
    const unsigned vsm_sa = (unsigned)__cvta_generic_to_shared(Vsm);
    const unsigned laneK = 2 * ((lane & 7) * ALD + 8 * (lane >> 3));
    const unsigned laneV = 2 * ((((lane >> 4) * 8) + (lane & 7)) * VLD
                                + 8 * ((lane >> 3) & 1));

    float m0 = -INFINITY, m1 = -INFINITY, l0 = 0.f, l1 = 0.f;
    float o[16][4];
#pragma unroll
    for (int n = 0; n < 16; n++)
#pragma unroll
        for (int u = 0; u < 4; u++) o[n][u] = 0.f;

    const int NT = (NTOK / NSPL) / TK;   // 64 tiles
    for (int kt = 0; kt < NT; kt++) {
        const int cur = kt & 1;
        if (kt + 1 < NT) {
            __nv_bfloat16* kd = Ksm + (cur ^ 1) * TK * ALD;
            __nv_bfloat16* vd = Vsm + (cur ^ 1) * C2 * VLD;
            const size_t kb = (size_t)kofs + (size_t)(kt + 1) * TK;
#pragma unroll
            for (int t = 0; t < 4; t++) {
                int e = (tid + t * 128) * 8;
                int r = e >> 7, d = e & 127;
                cpasync16(&kd[r * ALD + d], Kg + (kb + r) * C2 + d);
            }
#pragma unroll
            for (int t = 0; t < 4; t++) {
                int e = (tid + t * 128) * 8;
                int r = e >> 5, d = e & 31;
                cpasync16(&vd[r * VLD + d], VTg + (size_t)r * NTOK + kb + d);
            }
            asm volatile("cp.async.commit_group;\n");
            asm volatile("cp.async.wait_group 1;\n");
        } else {
            asm volatile("cp.async.wait_group 0;\n");
        }
        __syncthreads();

        const unsigned kb_sa = ksm_sa + cur * (TK * ALD * 2);
        const unsigned vb_sa = vsm_sa + cur * (C2 * VLD * 2);

        // S = Q K^T : 4 n-tiles (32 keys) x 8 k-steps
        float s[4][4];
#pragma unroll
        for (int j = 0; j < 4; j++) {
            s[j][0] = 0.f; s[j][1] = 0.f; s[j][2] = 0.f; s[j][3] = 0.f;
        }
#pragma unroll
        for (int j = 0; j < 4; j++) {
            unsigned rowb = kb_sa + laneK + j * (16 * ALD);
#pragma unroll
            for (int tt = 0; tt < 4; tt++) {
                unsigned b0, b1, b2, b3;
                ldsm4(b0, b1, b2, b3, rowb + tt * 64);
                mma16816(s[j], qa[2 * tt],     b0, b1);
                mma16816(s[j], qa[2 * tt + 1], b2, b3);
            }
        }

        // online softmax
        float rmax0 = s[0][0], rmax1 = s[0][2];
#pragma unroll
        for (int j = 0; j < 4; j++) {
            rmax0 = fmaxf(rmax0, fmaxf(s[j][0], s[j][1]));
            rmax1 = fmaxf(rmax1, fmaxf(s[j][2], s[j][3]));
        }
        rmax0 = fmaxf(rmax0, __shfl_xor_sync(0xffffffffu, rmax0, 1));
        rmax0 = fmaxf(rmax0, __shfl_xor_sync(0xffffffffu, rmax0, 2));
        rmax1 = fmaxf(rmax1, __shfl_xor_sync(0xffffffffu, rmax1, 1));
        rmax1 = fmaxf(rmax1, __shfl_xor_sync(0xffffffffu, rmax1, 2));

        float mn0 = fmaxf(m0, rmax0), mn1 = fmaxf(m1, rmax1);
        float sc0 = __expf(m0 - mn0), sc1 = __expf(m1 - mn1);
        m0 = mn0; m1 = mn1;

        float rs0 = 0.f, rs1 = 0.f;
#pragma unroll
        for (int j = 0; j < 4; j++) {
            s[j][0] = __expf(s[j][0] - mn0); rs0 += s[j][0];
            s[j][1] = __expf(s[j][1] - mn0); rs0 += s[j][1];
            s[j][2] = __expf(s[j][2] - mn1); rs1 += s[j][2];
            s[j][3] = __expf(s[j][3] - mn1); rs1 += s[j][3];
        }
        rs0 += __shfl_xor_sync(0xffffffffu, rs0, 1);
        rs0 += __shfl_xor_sync(0xffffffffu, rs0, 2);
        rs1 += __shfl_xor_sync(0xffffffffu, rs1, 1);
        rs1 += __shfl_xor_sync(0xffffffffu, rs1, 2);
        l0 = l0 * sc0 + rs0;
        l1 = l1 * sc1 + rs1;
#pragma unroll
        for (int n = 0; n < 16; n++) {
            o[n][0] *= sc0; o[n][1] *= sc0;
            o[n][2] *= sc1; o[n][3] *= sc1;
        }

        // O += P @ V : 2 k-steps over 32 keys
#pragma unroll
        for (int t = 0; t < 2; t++) {
            unsigned pa[4];
            pa[0] = pack_bf16x2(s[2*t  ][0], s[2*t  ][1]);
            pa[1] = pack_bf16x2(s[2*t  ][2], s[2*t  ][3]);
            pa[2] = pack_bf16x2(s[2*t+1][0], s[2*t+1][1]);
            pa[3] = pack_bf16x2(s[2*t+1][2], s[2*t+1][3]);
#pragma unroll
            for (int nq = 0; nq < 8; nq++) {
                unsigned b0, b1, b2, b3;
                ldsm4(b0, b1, b2, b3, vb_sa + laneV + nq * (32 * VLD) + t * 32);
                mma16816(o[2 * nq],     pa, b0, b1);
                mma16816(o[2 * nq + 1], pa, b2, b3);
            }
        }
        __syncthreads();
    }

    float* Op = Oa + (size_t)spl * NTOK * C2;
#pragma unroll
    for (int n = 0; n < 16; n++) {
        int c = 8 * n + 2 * mq;
        *(float2*)(Op + (size_t)(q0 + r0 + g    ) * C2 + c) = make_float2(o[n][0], o[n][1]);
        *(float2*)(Op + (size_t)(q0 + r0 + g + 8) * C2 + c) = make_float2(o[n][2], o[n][3]);
    }
    if (mq == 0) {
        float* mlp = Ml + (size_t)spl * NTOK * 2;
        *(float2*)(mlp + (size_t)(q0 + r0 + g    ) * 2) = make_float2(m0, l0);
        *(float2*)(mlp + (size_t)(q0 + r0 + g + 8) * 2) = make_float2(m1, l1);
    }
}

// ---------------------------------------------------------------------------
// Merge NSPL=4 split-KV partials -> normalized bf16 attention output.
// ---------------------------------------------------------------------------
__global__ __launch_bounds__(256) void attn_merge(
    const float* __restrict__ Oa, const float* __restrict__ Ml,
    __nv_bfloat16* __restrict__ Outb)
{
    const int tid = blockIdx.x * 256 + threadIdx.x;   // 32768 threads
#pragma unroll
    for (int t = 0; t < 8; t++) {
        int idx = (tid + t * 32768) * 4;
        int row = idx >> 7;

        float2 ml[NSPL];
        float mm = -INFINITY;
#pragma unroll
        for (int s = 0; s < NSPL; s++) {
            ml[s] = *(const float2*)(Ml + ((size_t)s * NTOK + row) * 2);
            mm = fmaxf(mm, ml[s].x);
        }
        float w[NSPL];
        float den = 0.f;
#pragma unroll
        for (int s = 0; s < NSPL; s++) {
            w[s] = __expf(ml[s].x - mm);
            den += w[s] * ml[s].y;
        }
        float inv = 1.f / den;

        float4 r = make_float4(0.f, 0.f, 0.f, 0.f);
#pragma unroll
        for (int s = 0; s < NSPL; s++) {
            float ws2 = w[s] * inv;
            float4 o = *(const float4*)(Oa + (size_t)s * NTOK * C2 + idx);
            r.x += o.x * ws2; r.y += o.y * ws2;
            r.z += o.z * ws2; r.w += o.w * ws2;
        }
        uint2 u;
        u.x = pack_bf16x2(r.x, r.y);
        u.y = pack_bf16x2(r.z, r.w);
        *(uint2*)(Outb + idx) = u;
    }
}

// ---------------------------------------------------------------------------
// Tensor-core mask GEMM + fused epilogue (unchanged from R12).
// ---------------------------------------------------------------------------
#define MASK_SMEM ((64*WLD + 128*WLD) * 2)

__global__ __launch_bounds__(128) void mask_mma(
    const __nv_bfloat16* __restrict__ Ab,
    const __nv_bfloat16* __restrict__ Wmb,
    float* __restrict__ C,
    const float* __restrict__ sp, const float* __restrict__ xres)
{
    extern __shared__ __align__(16) __nv_bfloat16 msm[];
    __nv_bfloat16* as = msm;               // 64 * WLD
    __nv_bfloat16* wm = msm + 64 * WLD;    // 128 * WLD

    const int tid  = threadIdx.x;
    const int warp = tid >> 5;
    const int lane = tid & 31;
    const int g    = lane >> 2;
    const int mq   = lane & 3;
    const int m0   = blockIdx.x * 64;
    const int col0 = blockIdx.y * 128;
    const int r0   = warp * 16;

#pragma unroll
    for (int t = 0; t < 8; t++) {
        int e = (tid + t * 128) * 8;
        int r = e >> 7, d = e & 127;
        *(uint4*)&as[r * WLD + d] = *(const uint4*)(Ab + (size_t)(m0 + r) * C2 + d);
    }
#pragma unroll
    for (int t = 0; t < 16; t++) {
        int e = (tid + t * 128) * 8;
        int r = e >> 7, c = e & 127;
        *(uint4*)&wm[r * WLD + c] = *(const uint4*)(Wmb + (size_t)r * CIN + col0 + c);
    }
    __syncthreads();

    unsigned qa[8][4];
#pragma unroll
    for (int t = 0; t < 8; t++) {
        int k0 = t * 16;
        qa[t][0] = *(const unsigned*)&as[(r0 + g    ) * WLD + k0 + 2 * mq];
        qa[t][1] = *(const unsigned*)&as[(r0 + g + 8) * WLD + k0 + 2 * mq];
        qa[t][2] = *(const unsigned*)&as[(r0 + g    ) * WLD + k0 + 8 + 2 * mq];
        qa[t][3] = *(const unsigned*)&as[(r0 + g + 8) * WLD + k0 + 8 + 2 * mq];
    }

    float acc[16][4];
#pragma unroll
    for (int n = 0; n < 16; n++)
#pragma unroll
        for (int u = 0; u < 4; u++) acc[n][u] = 0.f;

    const unsigned wm_sa = (unsigned)__cvta_generic_to_shared(wm);
    const unsigned laneW = 2 * (((lane & 7) + 8 * ((lane >> 3) & 1)) * WLD
                                + 8 * (lane >> 4));

#pragma unroll
    for (int t = 0; t < 8; t++) {
#pragma unroll
        for (int nq = 0; nq < 8; nq++) {
            unsigned b0, b1, b2, b3;
            ldsm4t(b0, b1, b2, b3, wm_sa + laneW + t * (32 * WLD) + nq * 32);
            mma16816(acc[2 * nq],     qa[t], b0, b1);
            mma16816(acc[2 * nq + 1], qa[t], b2, b3);
        }
    }

    const int ra = m0 + r0 + g, rb = ra + 8;
    const float spa = sp[ra], spb = sp[rb];
#pragma unroll
    for (int n = 0; n < 16; n++) {
        int c0 = col0 + 8 * n + 2 * mq;
        float2 xa = *(const float2*)(xres + (size_t)ra * CIN + c0);
        float2 xb2 = *(const float2*)(xres + (size_t)rb * CIN + c0);
        float2 va = make_float2(acc[n][0] * spa + xa.x, acc[n][1] * spa + xa.y);
        float2 vb = make_float2(acc[n][2] * spb + xb2.x, acc[n][3] * spb + xb2.y);
        *(float2*)(C + (size_t)ra * CIN + c0) = va;
        *(float2*)(C + (size_t)rb * CIN + c0) = vb;
    }
}

// ---------------------------------------------------------------------------
// Launcher with fork-join stream overlap.
//   stream0: conv_x -> (fork) conv_w -> proj -> attn -> merge -> [join] mask
//   aux:     (after conv_x) dense_mma -> dense_softmax
// ---------------------------------------------------------------------------
static cudaStream_t s_aux = nullptr;
static cudaEvent_t  s_evFork = nullptr, s_evJoin = nullptr;

extern "C" void kernel_launch(void* const* d_in, const int* in_sizes, int n_in,
                              void* d_out, int out_size)
{
    (void)in_sizes; (void)n_in; (void)out_size;
    const float* x       = (const float*)d_in[0];
    const float* W_theta = (const float*)d_in[1];
    const float* b_theta = (const float*)d_in[2];
    const float* W_phi   = (const float*)d_in[3];
    const float* b_phi   = (const float*)d_in[4];
    const float* W_alpha = (const float*)d_in[5];
    const float* b_alpha = (const float*)d_in[6];
    const float* W_mask  = (const float*)d_in[7];
    const float* W_dense = (const float*)d_in[8];
    const float* b_dense = (const float*)d_in[9];
    float* out = (float*)d_out;

    if (!s_aux) {
        cudaStreamCreateWithFlags(&s_aux, cudaStreamNonBlocking);
        cudaEventCreateWithFlags(&s_evFork, cudaEventDisableTiming);
        cudaEventCreateWithFlags(&s_evJoin, cudaEventDisableTiming);
    }

    __nv_bfloat16 *xb, *wtb, *wpb, *wab, *wmb, *q, *k, *vT, *attnb;
    float *oa, *ml, *part, *sp;
    cudaGetSymbolAddress((void**)&xb,    g_xb);
    cudaGetSymbolAddress((void**)&wtb,   g_wtb);
    cudaGetSymbolAddress((void**)&wpb,   g_wpb);
    cudaGetSymbolAddress((void**)&wab,   g_wab);
    cudaGetSymbolAddress((void**)&wmb,   g_wmb);
    cudaGetSymbolAddress((void**)&q,     g_q);
    cudaGetSymbolAddress((void**)&k,     g_k);
    cudaGetSymbolAddress((void**)&vT,    g_vT);
    cudaGetSymbolAddress((void**)&oa,    g_oa);
    cudaGetSymbolAddress((void**)&ml,    g_ml);
    cudaGetSymbolAddress((void**)&attnb, g_attnb);
    cudaGetSymbolAddress((void**)&part,  g_part);
    cudaGetSymbolAddress((void**)&sp,    g_sp);

    cudaFuncSetAttribute(attn_mma_kernel,
                         cudaFuncAttributeMaxDynamicSharedMemorySize,
                         ATTN_SMEM_BYTES);
    cudaFuncSetAttribute(proj_mma,
                         cudaFuncAttributeMaxDynamicSharedMemorySize,
                         PROJ_SMEM);
    cudaFuncSetAttribute(mask_mma,
                         cudaFuncAttributeMaxDynamicSharedMemorySize,
                         MASK_SMEM);

    // x -> bf16 (needed by both chains)
    conv_x<<<NTOK * CIN / (256 * 8), 256>>>(x, xb);

    // ---- fork: dense chain on auxiliary stream (tensor-core split-K) ----
    cudaEventRecord(s_evFork, 0);
    cudaStreamWaitEvent(s_aux, s_evFork, 0);
    dense_mma<<<dim3(8, DNCH), 128, 0, s_aux>>>(xb, W_dense, part);
    dense_softmax<<<BATCH, 256, 0, s_aux>>>(part, b_dense, sp);
    cudaEventRecord(s_evJoin, s_aux);

    // ---- main chain ----
    conv_w<<<(4 * CIN * C2) / (256 * 8), 256>>>(W_theta, W_phi, W_alpha, W_mask,
                                                wtb, wpb, wab, wmb);
    proj_mma<<<dim3(128, 1, 3), 128, PROJ_SMEM>>>(xb, wtb, b_theta, wpb, b_phi,
                                                  wab, b_alpha, q, k, vT);
    attn_mma_kernel<<<dim3(NTOK / TQ, NSPL), 128, ATTN_SMEM_BYTES>>>(
        q, k, vT, oa, ml);
    attn_merge<<<128, 256>>>(oa, ml, attnb);

    // ---- join, then fused mask GEMM + gate + residual ----
    cudaStreamWaitEvent(0, s_evJoin, 0);
    mask_mma<<<dim3(128, 2), 128, MASK_SMEM>>>(attnb, wmb, out, sp, x);
}